// round 3
// baseline (speedup 1.0000x reference)
#include <cuda_runtime.h>
#include <math.h>

#define BB 16
#define NN 128
#define DD 64
#define BN  2048        // BB*NN
#define BND 131072      // BN*DD
#define BNDD 8388608    // BND*DD

// out layout: prediction[BND], target[BND], A_new[BN*NN], W1n[BNDD], W2n[BNDD], W3n[BNDD]
#define OFF_T  (BND)
#define OFF_A  (2*BND)
#define OFF_W1 (4*BND)            // 2*BND + BN*NN = 4*BND
#define OFF_W2 (OFF_W1 + BNDD)
#define OFF_W3 (OFF_W2 + BNDD)

// scratch (static device globals; no allocation)
__device__ float g_q[BND];
__device__ float g_k[BND];
__device__ float g_pm[64];
__device__ float g_pe[64];
__device__ float g_pe2[64];
__device__ float g_mag[BB];
__device__ float g_std;
__device__ unsigned g_cnt = 0;

__device__ __forceinline__ float wredMax(float v) {
    #pragma unroll
    for (int o = 16; o; o >>= 1) v = fmaxf(v, __shfl_xor_sync(0xffffffffu, v, o));
    return v;
}
__device__ __forceinline__ float wredSum(float v) {
    #pragma unroll
    for (int o = 16; o; o >>= 1) v += __shfl_xor_sync(0xffffffffu, v, o);
    return v;
}

// ---------------------------------------------------------------------------
// K1: per (b,n) three matvecs: raw_pred = state@W1, k = state@W2, q = state@W3
// plus prediction elementwise. 2048 blocks x 192 threads.
// ---------------------------------------------------------------------------
__global__ void __launch_bounds__(192) k1_qkp(
    const float* __restrict__ state,
    const float* __restrict__ W1, const float* __restrict__ W2, const float* __restrict__ W3,
    float* __restrict__ out)
{
    int bn = blockIdx.x;
    int t  = threadIdx.x;
    int x  = t >> 6;          // 0: W1(pred), 1: W2(k), 2: W3(q)
    int kk = t & 63;

    __shared__ float s[DD];
    if (t < DD) s[t] = state[bn * DD + t];
    __syncthreads();

    const float* Wp = (x == 0) ? W1 : ((x == 1) ? W2 : W3);
    const float* Wb = Wp + (size_t)bn * DD * DD + kk;
    float a0 = 0.f, a1 = 0.f;
    #pragma unroll
    for (int j = 0; j < DD; j += 2) {
        a0 += s[j]     * Wb[j * DD];
        a1 += s[j + 1] * Wb[(j + 1) * DD];
    }
    float acc = a0 + a1;

    if (x == 0) {
        float raw = acc - tanhf(acc) * 0.6f;
        out[bn * DD + kk] = tanhf(raw) * 1.8477590650225735f;  // sqrt(2+sqrt(2))
    } else if (x == 1) {
        g_k[bn * DD + kk] = acc;
    } else {
        g_q[bn * DD + kk] = acc;
    }
}

// ---------------------------------------------------------------------------
// K2: attention row per block: raw_A, dense softmax, keep-mask, renorm P,
// A_new (rows 0,1 zeroed), target = A_new @ output with env clamp.
// 2048 blocks x 128 threads. Target matvec split across all 128 threads.
// ---------------------------------------------------------------------------
__global__ void __launch_bounds__(128) k2_attn(
    const float* __restrict__ A,
    const float* __restrict__ noiseA,
    const float* __restrict__ outputv,
    const float* __restrict__ eye,
    const float* __restrict__ stomach,
    float* __restrict__ out)
{
    int bn = blockIdx.x;
    int b  = bn >> 7;
    int n  = bn & 127;
    int m  = threadIdx.x;

    if (n < 2) {
        out[OFF_A + (size_t)bn * NN + m] = 0.f;
        if (m < DD) out[OFF_T + bn * DD + m] = (n == 0) ? eye[b * DD + m] : stomach[b * DD + m];
        return;
    }

    __shared__ float qs[DD];
    __shared__ float red[4];
    __shared__ float anew[NN];
    __shared__ float tpart[NN];

    if (m < DD) qs[m] = g_q[bn * DD + m];
    __syncthreads();

    const float4* krow = (const float4*)(g_k + (size_t)(b * NN + m) * DD);
    float dot = 0.f;
    #pragma unroll
    for (int i = 0; i < DD / 4; i++) {
        float4 v = krow[i];
        dot += qs[4*i] * v.x + qs[4*i+1] * v.y + qs[4*i+2] * v.z + qs[4*i+3] * v.w;
    }
    float raw = dot * 0.125f + noiseA[(size_t)bn * NN + m] * 1e-5f;

    // row max
    float v = wredMax(raw);
    if ((m & 31) == 0) red[m >> 5] = v;
    __syncthreads();
    float rowmax = fmaxf(fmaxf(red[0], red[1]), fmaxf(red[2], red[3]));
    __syncthreads();

    float e = expf(raw - rowmax);
    v = wredSum(e);
    if ((m & 31) == 0) red[m >> 5] = v;
    __syncthreads();
    float sum = red[0] + red[1] + red[2] + red[3];
    __syncthreads();

    float pd = e / sum;
    v = wredMax(pd);
    if ((m & 31) == 0) red[m >> 5] = v;
    __syncthreads();
    float maxpd = fmaxf(fmaxf(red[0], red[1]), fmaxf(red[2], red[3]));
    __syncthreads();

    bool keep = (pd > (1.0f / 129.0f)) || (pd == maxpd);
    float ek = keep ? e : 0.f;
    v = wredSum(ek);
    if ((m & 31) == 0) red[m >> 5] = v;
    __syncthreads();
    float sum2 = red[0] + red[1] + red[2] + red[3];
    __syncthreads();

    float P  = ek / sum2;
    float an = A[(size_t)bn * NN + m] * 0.99f + P * 0.01f;
    out[OFF_A + (size_t)bn * NN + m] = an;
    anew[m] = an;
    __syncthreads();

    // target: split 128-length mm loop over both halves of the block
    {
        int col  = m & 63;
        int half = m >> 6;           // 0 or 1
        int mm0  = half * 64;
        float acc = 0.f;
        #pragma unroll 8
        for (int mm = mm0; mm < mm0 + 64; mm++)
            acc += anew[mm] * outputv[(size_t)(b * NN + mm) * DD + col];
        tpart[m] = acc;
    }
    __syncthreads();
    if (m < DD) out[OFF_T + bn * DD + m] = tpart[m] + tpart[m + 64];
}

// ---------------------------------------------------------------------------
// K3: per-b state magnitude + global err std (ddof=1), fused via last-block.
// 64 blocks (4 per b) x 256 threads.
// ---------------------------------------------------------------------------
__global__ void __launch_bounds__(256) k3_stats(
    const float* __restrict__ state, const float* __restrict__ out)
{
    int blk = blockIdx.x;
    int b   = blk >> 2;
    int c   = blk & 3;
    int t   = threadIdx.x;

    float am = 0.f, ae = 0.f, ae2 = 0.f;
    int base = b * NN * DD + c * (NN * DD / 4);
    #pragma unroll 2
    for (int idx = t; idx < NN * DD / 4; idx += 256) {
        int g = base + idx;
        am += fabsf(state[g]);
        float e = out[g] - out[OFF_T + g];
        ae += e; ae2 += e * e;
    }
    am = wredSum(am); ae = wredSum(ae); ae2 = wredSum(ae2);
    __shared__ float s0[8], s1[8], s2[8];
    int w = t >> 5;
    if ((t & 31) == 0) { s0[w] = am; s1[w] = ae; s2[w] = ae2; }
    __syncthreads();
    if (t < 32) {
        float a  = (t < 8) ? s0[t] : 0.f;
        float bb = (t < 8) ? s1[t] : 0.f;
        float cc = (t < 8) ? s2[t] : 0.f;
        a = wredSum(a); bb = wredSum(bb); cc = wredSum(cc);
        if (t == 0) { g_pm[blk] = a; g_pe[blk] = bb; g_pe2[blk] = cc; }
    }

    // last-block final reduction
    __shared__ int isLast;
    __syncthreads();
    if (t == 0) {
        __threadfence();
        unsigned old = atomicAdd(&g_cnt, 1u);
        isLast = (old == 63u) ? 1 : 0;
    }
    __syncthreads();
    if (isLast) {
        if (t < BB)
            g_mag[t] = g_pm[4*t] + g_pm[4*t+1] + g_pm[4*t+2] + g_pm[4*t+3];
        if (t < 64) {
            float e  = g_pe[t];
            float e2 = g_pe2[t];
            e = wredSum(e); e2 = wredSum(e2);
            __shared__ float r0[2], r1[2];
            if ((t & 31) == 0) { r0[t >> 5] = e; r1[t >> 5] = e2; }
            __syncwarp();
            if (t == 0) {
                // wait for warp1's shared write: use a light spin-free approach via bar
            }
        }
        __syncthreads();
        if (t == 0) {
            __shared__ float r0x[2], r1x[2];  // placeholder; real values recomputed below
        }
        // simpler deterministic final: thread 0 serially sums the 64 partials
        if (t == 0) {
            float e = 0.f, e2 = 0.f;
            #pragma unroll
            for (int i = 0; i < 64; i++) { e += g_pe[i]; e2 += g_pe2[i]; }
            const float M = (float)BND;
            float var = (e2 - e * e / M) / (M - 1.0f);
            g_std = sqrtf(fmaxf(var, 0.f));
            g_cnt = 0u;   // reset for next graph replay
        }
    }
}

// ---------------------------------------------------------------------------
// K5: fused K4 prelude (coef/noisy per bn, recomputed per quarter-tile by
// warp 0) + grads + momentum + gaussian mask + W update + row rms.
// 8192 blocks x 256 threads; block handles 16 rows (quarter of a bn tile).
// ---------------------------------------------------------------------------
__device__ __forceinline__ float newW(float w, float wlat, float m, float h, float g) {
    float grad = h + 0.01f * wlat - 0.01f * w;     // LAT_DECAY*W_lat - WD*W_self
    return w + 0.0033f * (m * 0.4f + 0.6f * grad * g);
}

__global__ void __launch_bounds__(256) k5_update(
    const float* __restrict__ W1, const float* __restrict__ W2, const float* __restrict__ W3,
    const float* __restrict__ M1, const float* __restrict__ M2, const float* __restrict__ M3,
    const float* __restrict__ state,
    const float* __restrict__ Ebase,
    const float* __restrict__ n1raw,
    const float* __restrict__ n2raw,
    const int* __restrict__ stepc,
    float* __restrict__ out)
{
    int t    = threadIdx.x;
    int tx   = t & 15;
    int rloc = t >> 4;                 // 0..15
    int bn   = blockIdx.x >> 2;
    int b    = bn >> 7;
    int row  = bn * DD + (blockIdx.x & 3) * 16 + rloc;   // global (b,n,i) row
    size_t b4 = (size_t)row * 16 + tx;

    // issue the big loads first; they fly during the prelude
    float4 w1 = ((const float4*)W1)[b4];
    float4 w2 = ((const float4*)W2)[b4];
    float4 w3 = ((const float4*)W3)[b4];
    float4 m1 = ((const float4*)M1)[b4];
    float4 m2 = ((const float4*)M2)[b4];
    float4 m3 = ((const float4*)M3)[b4];

    __shared__ float s_coef[DD];
    __shared__ float s_ns[DD];

    // ---- prelude: warp 0, lane l handles i = l and i = l+32 ----
    if (t < 32) {
        int g0 = bn * DD + t;
        int g1 = g0 + 32;
        float errA = out[g0] - out[OFF_T + g0];
        float errB = out[g1] - out[OFF_T + g1];

        float mx = wredMax(fmaxf(errA, errB));
        float exA = expf(errA - mx), exB = expf(errB - mx);
        float sm = wredSum(exA + exB);
        float EcA = exA / sm, EcB = exB / sm;

        float Eb0A = Ebase[g0], Eb0B = Ebase[g1];
        float EbA = (Eb0A == 0.f) ? EcA : Eb0A;
        float EbB = (Eb0B == 0.f) ? EcB : Eb0B;
        EbA = EbA * 0.95f + 0.05f * EcA;
        EbB = EbB * 0.95f + 0.05f * EcB;
        float advA = EcA - EbA, advB = EcB - EbB;
        float plA = 1.f + advA * rsqrtf(advA * advA + 1e-6f);
        float plB = 1.f + advB * rsqrtf(advB * advB + 1e-6f);
        float mkA = (EbA > 0.f) ? 1.f : 0.f;
        float mkB = (EbB > 0.f) ? 1.f : 0.f;

        float inv_mag = 1.f / (1.f + g_mag[b]);
        float sd = g_std * 0.8f;
        float nsA = state[g0] + n1raw[g0] * inv_mag + n2raw[g0] * sd;
        float nsB = state[g1] + n1raw[g1] * inv_mag + n2raw[g1] * sd;

        float se2 = wredSum(errA * errA + errB * errB);
        float sn2 = wredSum(nsA * nsA + nsB * nsB);
        float rn = rsqrtf((se2 * (1.f / DD)) * (sn2 * (1.f / DD)) + 1e-6f);

        s_coef[t]      = -errA * rn * plA * mkA;
        s_coef[t + 32] = -errB * rn * plB * mkB;
        s_ns[t]        = nsA;
        s_ns[t + 32]   = nsB;
    }
    __syncthreads();

    float  c  = s_coef[(blockIdx.x & 3) * 16 + rloc];
    float4 ns = ((const float4*)s_ns)[tx];

    float scf    = (float)(*stepc) + 1.0f;
    float center = fmodf(scf * 0.5f, 64.0f);
    int j0 = tx * 4;
    float4 gm;
    {
        float d;
        d = fabsf((float)(j0 + 0) - center); d = fminf(d, 64.f - d); gm.x = expf(-d * d / 0.020001f);
        d = fabsf((float)(j0 + 1) - center); d = fminf(d, 64.f - d); gm.y = expf(-d * d / 0.020001f);
        d = fabsf((float)(j0 + 2) - center); d = fminf(d, 64.f - d); gm.z = expf(-d * d / 0.020001f);
        d = fabsf((float)(j0 + 3) - center); d = fminf(d, 64.f - d); gm.w = expf(-d * d / 0.020001f);
    }

    float4 t1, t2, t3;
    t1.x = newW(w1.x, w3.x, m1.x, c * ns.x, gm.x);
    t1.y = newW(w1.y, w3.y, m1.y, c * ns.y, gm.y);
    t1.z = newW(w1.z, w3.z, m1.z, c * ns.z, gm.z);
    t1.w = newW(w1.w, w3.w, m1.w, c * ns.w, gm.w);
    t2.x = newW(w2.x, w1.x, m2.x, c * ns.x, gm.x);
    t2.y = newW(w2.y, w1.y, m2.y, c * ns.y, gm.y);
    t2.z = newW(w2.z, w1.z, m2.z, c * ns.z, gm.z);
    t2.w = newW(w2.w, w1.w, m2.w, c * ns.w, gm.w);
    t3.x = newW(w3.x, w2.x, m3.x, c * ns.x, gm.x);
    t3.y = newW(w3.y, w2.y, m3.y, c * ns.y, gm.y);
    t3.z = newW(w3.z, w2.z, m3.z, c * ns.z, gm.z);
    t3.w = newW(w3.w, w2.w, m3.w, c * ns.w, gm.w);

    float s1 = t1.x*t1.x + t1.y*t1.y + t1.z*t1.z + t1.w*t1.w;
    float s2 = t2.x*t2.x + t2.y*t2.y + t2.z*t2.z + t2.w*t2.w;
    float s3 = t3.x*t3.x + t3.y*t3.y + t3.z*t3.z + t3.w*t3.w;
    #pragma unroll
    for (int o = 8; o; o >>= 1) {
        s1 += __shfl_xor_sync(0xffffffffu, s1, o);
        s2 += __shfl_xor_sync(0xffffffffu, s2, o);
        s3 += __shfl_xor_sync(0xffffffffu, s3, o);
    }
    float r1 = rsqrtf(s1 * (1.f / 64.f) + 1e-6f);
    float r2 = rsqrtf(s2 * (1.f / 64.f) + 1e-6f);
    float r3 = rsqrtf(s3 * (1.f / 64.f) + 1e-6f);

    float4 o1 = { t1.x*r1, t1.y*r1, t1.z*r1, t1.w*r1 };
    float4 o2 = { t2.x*r2, t2.y*r2, t2.z*r2, t2.w*r2 };
    float4 o3 = { t3.x*r3, t3.y*r3, t3.z*r3, t3.w*r3 };
    ((float4*)(out + OFF_W1))[b4] = o1;
    ((float4*)(out + OFF_W2))[b4] = o2;
    ((float4*)(out + OFF_W3))[b4] = o3;
}

// ---------------------------------------------------------------------------
extern "C" void kernel_launch(void* const* d_in, const int* in_sizes, int n_in,
                              void* d_out, int out_size)
{
    const float* eye     = (const float*)d_in[0];
    const float* stomach = (const float*)d_in[1];
    const float* state   = (const float*)d_in[2];
    const float* outputv = (const float*)d_in[3];
    const float* W1      = (const float*)d_in[4];
    const float* W2      = (const float*)d_in[5];
    const float* W3      = (const float*)d_in[6];
    const float* M1      = (const float*)d_in[7];
    const float* M2      = (const float*)d_in[8];
    const float* M3      = (const float*)d_in[9];
    const float* Ebase   = (const float*)d_in[10];
    const float* A       = (const float*)d_in[11];
    const float* noiseA  = (const float*)d_in[12];
    const float* n1raw   = (const float*)d_in[13];
    const float* n2raw   = (const float*)d_in[14];
    const int*   stepc   = (const int*)d_in[15];
    float* out = (float*)d_out;

    k1_qkp<<<BN, 192>>>(state, W1, W2, W3, out);
    k2_attn<<<BN, 128>>>(A, noiseA, outputv, eye, stomach, out);
    k3_stats<<<64, 256>>>(state, out);
    k5_update<<<BND / 16, 256>>>(W1, W2, W3, M1, M2, M3,
                                 state, Ebase, n1raw, n2raw, stepc, out);
}

// round 4
// speedup vs baseline: 1.1312x; 1.1312x over previous
#include <cuda_runtime.h>
#include <math.h>

#define BB 16
#define NN 128
#define DD 64
#define BN  2048        // BB*NN
#define BND 131072      // BN*DD
#define BNDD 8388608    // BND*DD

// out layout: prediction[BND], target[BND], A_new[BN*NN], W1n[BNDD], W2n[BNDD], W3n[BNDD]
#define OFF_T  (BND)
#define OFF_A  (2*BND)
#define OFF_W1 (4*BND)            // 2*BND + BN*NN = 4*BND
#define OFF_W2 (OFF_W1 + BNDD)
#define OFF_W3 (OFF_W2 + BNDD)

// scratch (static device globals; no allocation)
__device__ float g_q[BND];
__device__ float g_k[BND];
__device__ float g_coef[BND];
__device__ float g_noisy[BND];
__device__ float g_pm[64];
__device__ float g_pe[64];
__device__ float g_pe2[64];
__device__ float g_mag[BB];
__device__ float g_gmask[DD];
__device__ float g_std;
__device__ unsigned g_cnt = 0;

__device__ __forceinline__ float wredMax(float v) {
    #pragma unroll
    for (int o = 16; o; o >>= 1) v = fmaxf(v, __shfl_xor_sync(0xffffffffu, v, o));
    return v;
}
__device__ __forceinline__ float wredSum(float v) {
    #pragma unroll
    for (int o = 16; o; o >>= 1) v += __shfl_xor_sync(0xffffffffu, v, o);
    return v;
}

// ---------------------------------------------------------------------------
// K1: per (b,n) three matvecs: raw_pred = state@W1, k = state@W2, q = state@W3
// plus prediction elementwise. 2048 blocks x 192 threads.
// ---------------------------------------------------------------------------
__global__ void __launch_bounds__(192) k1_qkp(
    const float* __restrict__ state,
    const float* __restrict__ W1, const float* __restrict__ W2, const float* __restrict__ W3,
    float* __restrict__ out)
{
    int bn = blockIdx.x;
    int t  = threadIdx.x;
    int x  = t >> 6;          // 0: W1(pred), 1: W2(k), 2: W3(q)
    int kk = t & 63;

    __shared__ float s[DD];
    if (t < DD) s[t] = state[bn * DD + t];
    __syncthreads();

    const float* Wp = (x == 0) ? W1 : ((x == 1) ? W2 : W3);
    const float* Wb = Wp + (size_t)bn * DD * DD + kk;
    float a0 = 0.f, a1 = 0.f;
    #pragma unroll
    for (int j = 0; j < DD; j += 2) {
        a0 += s[j]     * Wb[j * DD];
        a1 += s[j + 1] * Wb[(j + 1) * DD];
    }
    float acc = a0 + a1;

    if (x == 0) {
        float raw = acc - tanhf(acc) * 0.6f;
        out[bn * DD + kk] = tanhf(raw) * 1.8477590650225735f;  // sqrt(2+sqrt(2))
    } else if (x == 1) {
        g_k[bn * DD + kk] = acc;
    } else {
        g_q[bn * DD + kk] = acc;
    }
}

// ---------------------------------------------------------------------------
// K2: attention row per block: raw_A, dense softmax, keep-mask, renorm P,
// A_new (rows 0,1 zeroed), target = A_new @ output with env clamp.
// 2048 blocks x 128 threads.
// ---------------------------------------------------------------------------
__global__ void __launch_bounds__(128) k2_attn(
    const float* __restrict__ A,
    const float* __restrict__ noiseA,
    const float* __restrict__ outputv,
    const float* __restrict__ eye,
    const float* __restrict__ stomach,
    float* __restrict__ out)
{
    int bn = blockIdx.x;
    int b  = bn >> 7;
    int n  = bn & 127;
    int m  = threadIdx.x;

    if (n < 2) {
        out[OFF_A + (size_t)bn * NN + m] = 0.f;
        if (m < DD) out[OFF_T + bn * DD + m] = (n == 0) ? eye[b * DD + m] : stomach[b * DD + m];
        return;
    }

    __shared__ float qs[DD];
    __shared__ float red[4];
    __shared__ float anew[NN];
    __shared__ float tpart[NN];

    if (m < DD) qs[m] = g_q[bn * DD + m];
    __syncthreads();

    const float4* krow = (const float4*)(g_k + (size_t)(b * NN + m) * DD);
    float dot = 0.f;
    #pragma unroll
    for (int i = 0; i < DD / 4; i++) {
        float4 v = krow[i];
        dot += qs[4*i] * v.x + qs[4*i+1] * v.y + qs[4*i+2] * v.z + qs[4*i+3] * v.w;
    }
    float raw = dot * 0.125f + noiseA[(size_t)bn * NN + m] * 1e-5f;

    // row max
    float v = wredMax(raw);
    if ((m & 31) == 0) red[m >> 5] = v;
    __syncthreads();
    float rowmax = fmaxf(fmaxf(red[0], red[1]), fmaxf(red[2], red[3]));
    __syncthreads();

    float e = expf(raw - rowmax);
    v = wredSum(e);
    if ((m & 31) == 0) red[m >> 5] = v;
    __syncthreads();
    float sum = red[0] + red[1] + red[2] + red[3];
    __syncthreads();

    float pd = e / sum;
    v = wredMax(pd);
    if ((m & 31) == 0) red[m >> 5] = v;
    __syncthreads();
    float maxpd = fmaxf(fmaxf(red[0], red[1]), fmaxf(red[2], red[3]));
    __syncthreads();

    bool keep = (pd > (1.0f / 129.0f)) || (pd == maxpd);
    float ek = keep ? e : 0.f;
    v = wredSum(ek);
    if ((m & 31) == 0) red[m >> 5] = v;
    __syncthreads();
    float sum2 = red[0] + red[1] + red[2] + red[3];
    __syncthreads();

    float P  = ek / sum2;
    float an = A[(size_t)bn * NN + m] * 0.99f + P * 0.01f;
    out[OFF_A + (size_t)bn * NN + m] = an;
    anew[m] = an;
    __syncthreads();

    // target: split 128-length mm loop over both halves of the block
    {
        int col  = m & 63;
        int half = m >> 6;           // 0 or 1
        int mm0  = half * 64;
        float acc = 0.f;
        #pragma unroll 8
        for (int mm = mm0; mm < mm0 + 64; mm++)
            acc += anew[mm] * outputv[(size_t)(b * NN + mm) * DD + col];
        tpart[m] = acc;
    }
    __syncthreads();
    if (m < DD) out[OFF_T + bn * DD + m] = tpart[m] + tpart[m + 64];
}

// ---------------------------------------------------------------------------
// K3: per-b state magnitude + global err std (ddof=1) + gaussian column mask,
// fused via last-block-done. 64 blocks (4 per b) x 256 threads.
// ---------------------------------------------------------------------------
__global__ void __launch_bounds__(256) k3_stats(
    const float* __restrict__ state, const float* __restrict__ out,
    const int* __restrict__ stepc)
{
    int blk = blockIdx.x;
    int b   = blk >> 2;
    int c   = blk & 3;
    int t   = threadIdx.x;

    float am = 0.f, ae = 0.f, ae2 = 0.f;
    int base = b * NN * DD + c * (NN * DD / 4);
    #pragma unroll 2
    for (int idx = t; idx < NN * DD / 4; idx += 256) {
        int g = base + idx;
        am += fabsf(state[g]);
        float e = out[g] - out[OFF_T + g];
        ae += e; ae2 += e * e;
    }
    am = wredSum(am); ae = wredSum(ae); ae2 = wredSum(ae2);
    __shared__ float s0[8], s1[8], s2[8];
    int w = t >> 5;
    if ((t & 31) == 0) { s0[w] = am; s1[w] = ae; s2[w] = ae2; }
    __syncthreads();
    if (t < 32) {
        float a  = (t < 8) ? s0[t] : 0.f;
        float bb = (t < 8) ? s1[t] : 0.f;
        float cc = (t < 8) ? s2[t] : 0.f;
        a = wredSum(a); bb = wredSum(bb); cc = wredSum(cc);
        if (t == 0) { g_pm[blk] = a; g_pe[blk] = bb; g_pe2[blk] = cc; }
    }

    // last-block final reduction
    __shared__ int isLast;
    __syncthreads();
    if (t == 0) {
        __threadfence();
        unsigned old = atomicAdd(&g_cnt, 1u);
        isLast = (old == 63u) ? 1 : 0;
    }
    __syncthreads();
    if (isLast) {
        if (t < BB)
            g_mag[t] = g_pm[4*t] + g_pm[4*t+1] + g_pm[4*t+2] + g_pm[4*t+3];
        if (t < DD) {
            // travelling gaussian column mask
            float scf    = (float)(*stepc) + 1.0f;
            float center = fmodf(scf * 0.5f, 64.0f);
            float d = fabsf((float)t - center);
            d = fminf(d, 64.f - d);
            g_gmask[t] = expf(-d * d / 0.020001f);
        }
        if (t == 0) {
            float e = 0.f, e2 = 0.f;
            #pragma unroll
            for (int i = 0; i < 64; i++) { e += g_pe[i]; e2 += g_pe2[i]; }
            const float M = (float)BND;
            float var = (e2 - e * e / M) / (M - 1.0f);
            g_std = sqrtf(fmaxf(var, 0.f));
            g_cnt = 0u;   // reset for next graph replay
        }
    }
}

// ---------------------------------------------------------------------------
// K4: per (b,n): E_curr softmax over D, Eb EMA, plasticity/mask, noisy_state,
// outer-product rms factorization -> coef, noisy. 2048 blocks x 64 threads.
// ---------------------------------------------------------------------------
__global__ void __launch_bounds__(64) k4_coef(
    const float* __restrict__ state,
    const float* __restrict__ Ebase,
    const float* __restrict__ n1raw,
    const float* __restrict__ n2raw,
    const float* __restrict__ out)
{
    int bn = blockIdx.x;
    int b  = bn >> 7;
    int i  = threadIdx.x;
    int g  = bn * DD + i;

    __shared__ float red[2];
    float err = out[g] - out[OFF_T + g];

    float v = wredMax(err);
    if ((i & 31) == 0) red[i >> 5] = v;
    __syncthreads();
    float mx = fmaxf(red[0], red[1]);
    __syncthreads();
    float ex = expf(err - mx);
    v = wredSum(ex);
    if ((i & 31) == 0) red[i >> 5] = v;
    __syncthreads();
    float sm = red[0] + red[1];
    __syncthreads();
    float Ec = ex / sm;

    float Eb0 = Ebase[g];
    float Eb  = (Eb0 == 0.f) ? Ec : Eb0;       // bmask blend
    Eb = Eb * 0.95f + 0.05f * Ec;
    float adv   = Ec - Eb;
    float plast = 1.f + adv * rsqrtf(adv * adv + 1e-6f);   // 1 - R
    float mk    = (Eb > 0.f) ? 1.f : 0.f;

    float ns = state[g] + n1raw[g] / (1.f + g_mag[b]) + n2raw[g] * g_std * 0.8f;

    v = wredSum(err * err);
    if ((i & 31) == 0) red[i >> 5] = v;
    __syncthreads();
    float se2 = red[0] + red[1];
    __syncthreads();
    v = wredSum(ns * ns);
    if ((i & 31) == 0) red[i >> 5] = v;
    __syncthreads();
    float sn2 = red[0] + red[1];

    float rn = rsqrtf((se2 * (1.f / DD)) * (sn2 * (1.f / DD)) + 1e-6f);
    g_coef[g]  = -err * rn * plast * mk;
    g_noisy[g] = ns;
}

// ---------------------------------------------------------------------------
// K5: fused grads + momentum + gaussian column mask + W update + row rms.
// 16 threads per row (float4 each), 16 rows per 256-thread block.
// M loads streaming (__ldcs), W-new stores streaming (__stcs); W loads keep
// default policy to exploit L2 residency from k1.
// ---------------------------------------------------------------------------
__device__ __forceinline__ float newW(float w, float wlat, float m, float h, float g) {
    float grad = h + 0.01f * wlat - 0.01f * w;     // LAT_DECAY*W_lat - WD*W_self
    return w + 0.0033f * (m * 0.4f + 0.6f * grad * g);
}

__global__ void __launch_bounds__(256, 7) k5_update(
    const float* __restrict__ W1, const float* __restrict__ W2, const float* __restrict__ W3,
    const float* __restrict__ M1, const float* __restrict__ M2, const float* __restrict__ M3,
    float* __restrict__ out)
{
    int t   = threadIdx.x;
    int tx  = t & 15;
    int row = blockIdx.x * 16 + (t >> 4);  // 0..BND-1  (b,n,i)
    int bn  = row >> 6;
    size_t b4 = (size_t)row * 16 + tx;     // float4 index into (BND x D) matrices

    float4 w1 = ((const float4*)W1)[b4];
    float4 w2 = ((const float4*)W2)[b4];
    float4 w3 = ((const float4*)W3)[b4];

    float  c  = g_coef[row];
    float4 ns = ((const float4*)g_noisy)[bn * 16 + tx];
    float4 gm = ((const float4*)g_gmask)[tx];
    float4 h  = { c * ns.x, c * ns.y, c * ns.z, c * ns.w };

    // --- W1 update ---
    {
        float4 m1 = __ldcs(((const float4*)M1) + b4);
        float4 t1;
        t1.x = newW(w1.x, w3.x, m1.x, h.x, gm.x);
        t1.y = newW(w1.y, w3.y, m1.y, h.y, gm.y);
        t1.z = newW(w1.z, w3.z, m1.z, h.z, gm.z);
        t1.w = newW(w1.w, w3.w, m1.w, h.w, gm.w);
        float s1 = t1.x*t1.x + t1.y*t1.y + t1.z*t1.z + t1.w*t1.w;
        #pragma unroll
        for (int o = 8; o; o >>= 1) s1 += __shfl_xor_sync(0xffffffffu, s1, o);
        float r1 = rsqrtf(s1 * (1.f / 64.f) + 1e-6f);
        float4 o1 = { t1.x*r1, t1.y*r1, t1.z*r1, t1.w*r1 };
        __stcs(((float4*)(out + OFF_W1)) + b4, o1);
    }
    // --- W2 update ---
    {
        float4 m2 = __ldcs(((const float4*)M2) + b4);
        float4 t2;
        t2.x = newW(w2.x, w1.x, m2.x, h.x, gm.x);
        t2.y = newW(w2.y, w1.y, m2.y, h.y, gm.y);
        t2.z = newW(w2.z, w1.z, m2.z, h.z, gm.z);
        t2.w = newW(w2.w, w1.w, m2.w, h.w, gm.w);
        float s2 = t2.x*t2.x + t2.y*t2.y + t2.z*t2.z + t2.w*t2.w;
        #pragma unroll
        for (int o = 8; o; o >>= 1) s2 += __shfl_xor_sync(0xffffffffu, s2, o);
        float r2 = rsqrtf(s2 * (1.f / 64.f) + 1e-6f);
        float4 o2 = { t2.x*r2, t2.y*r2, t2.z*r2, t2.w*r2 };
        __stcs(((float4*)(out + OFF_W2)) + b4, o2);
    }
    // --- W3 update ---
    {
        float4 m3 = __ldcs(((const float4*)M3) + b4);
        float4 t3;
        t3.x = newW(w3.x, w2.x, m3.x, h.x, gm.x);
        t3.y = newW(w3.y, w2.y, m3.y, h.y, gm.y);
        t3.z = newW(w3.z, w2.z, m3.z, h.z, gm.z);
        t3.w = newW(w3.w, w2.w, m3.w, h.w, gm.w);
        float s3 = t3.x*t3.x + t3.y*t3.y + t3.z*t3.z + t3.w*t3.w;
        #pragma unroll
        for (int o = 8; o; o >>= 1) s3 += __shfl_xor_sync(0xffffffffu, s3, o);
        float r3 = rsqrtf(s3 * (1.f / 64.f) + 1e-6f);
        float4 o3 = { t3.x*r3, t3.y*r3, t3.z*r3, t3.w*r3 };
        __stcs(((float4*)(out + OFF_W3)) + b4, o3);
    }
}

// ---------------------------------------------------------------------------
extern "C" void kernel_launch(void* const* d_in, const int* in_sizes, int n_in,
                              void* d_out, int out_size)
{
    const float* eye     = (const float*)d_in[0];
    const float* stomach = (const float*)d_in[1];
    const float* state   = (const float*)d_in[2];
    const float* outputv = (const float*)d_in[3];
    const float* W1      = (const float*)d_in[4];
    const float* W2      = (const float*)d_in[5];
    const float* W3      = (const float*)d_in[6];
    const float* M1      = (const float*)d_in[7];
    const float* M2      = (const float*)d_in[8];
    const float* M3      = (const float*)d_in[9];
    const float* Ebase   = (const float*)d_in[10];
    const float* A       = (const float*)d_in[11];
    const float* noiseA  = (const float*)d_in[12];
    const float* n1raw   = (const float*)d_in[13];
    const float* n2raw   = (const float*)d_in[14];
    const int*   stepc   = (const int*)d_in[15];
    float* out = (float*)d_out;

    k1_qkp<<<BN, 192>>>(state, W1, W2, W3, out);
    k2_attn<<<BN, 128>>>(A, noiseA, outputv, eye, stomach, out);
    k3_stats<<<64, 256>>>(state, out, stepc);
    k4_coef<<<BN, DD>>>(state, Ebase, n1raw, n2raw, out);
    k5_update<<<BND / 16, 256>>>(W1, W2, W3, M1, M2, M3, out);
}

// round 5
// speedup vs baseline: 1.1627x; 1.0279x over previous
#include <cuda_runtime.h>
#include <math.h>

#define BB 16
#define NN 128
#define DD 64
#define BN  2048        // BB*NN
#define BND 131072      // BN*DD
#define BNDD 8388608    // BND*DD

// out layout: prediction[BND], target[BND], A_new[BN*NN], W1n[BNDD], W2n[BNDD], W3n[BNDD]
#define OFF_T  (BND)
#define OFF_A  (2*BND)
#define OFF_W1 (4*BND)            // 2*BND + BN*NN = 4*BND
#define OFF_W2 (OFF_W1 + BNDD)
#define OFF_W3 (OFF_W2 + BNDD)

// scratch (static device globals; no allocation)
__device__ float g_q[BND];
__device__ float g_k[BND];
__device__ float g_coef[BND];
__device__ float g_noisy[BND];
__device__ float g_pbn_m[BN];
__device__ float g_pbn_e[BN];
__device__ float g_pbn_e2[BN];
__device__ float g_mag[BB];
__device__ float g_gmask[DD];
__device__ float g_std;
__device__ unsigned g_cnt = 0;

__device__ __forceinline__ float wredMax(float v) {
    #pragma unroll
    for (int o = 16; o; o >>= 1) v = fmaxf(v, __shfl_xor_sync(0xffffffffu, v, o));
    return v;
}
__device__ __forceinline__ float wredSum(float v) {
    #pragma unroll
    for (int o = 16; o; o >>= 1) v += __shfl_xor_sync(0xffffffffu, v, o);
    return v;
}

// ---------------------------------------------------------------------------
// K1: per (b,n) three matvecs: raw_pred = state@W1, k = state@W2, q = state@W3
// plus prediction elementwise. 2048 blocks x 192 threads.
// ---------------------------------------------------------------------------
__global__ void __launch_bounds__(192) k1_qkp(
    const float* __restrict__ state,
    const float* __restrict__ W1, const float* __restrict__ W2, const float* __restrict__ W3,
    float* __restrict__ out)
{
    int bn = blockIdx.x;
    int t  = threadIdx.x;
    int x  = t >> 6;          // 0: W1(pred), 1: W2(k), 2: W3(q)
    int kk = t & 63;

    __shared__ float s[DD];
    if (t < DD) s[t] = state[bn * DD + t];
    __syncthreads();

    const float* Wp = (x == 0) ? W1 : ((x == 1) ? W2 : W3);
    const float* Wb = Wp + (size_t)bn * DD * DD + kk;
    float a0 = 0.f, a1 = 0.f;
    #pragma unroll
    for (int j = 0; j < DD; j += 2) {
        a0 += s[j]     * Wb[j * DD];
        a1 += s[j + 1] * Wb[(j + 1) * DD];
    }
    float acc = a0 + a1;

    if (x == 0) {
        float raw = acc - tanhf(acc) * 0.6f;
        out[bn * DD + kk] = tanhf(raw) * 1.8477590650225735f;  // sqrt(2+sqrt(2))
    } else if (x == 1) {
        g_k[bn * DD + kk] = acc;
    } else {
        g_q[bn * DD + kk] = acc;
    }
}

// ---------------------------------------------------------------------------
// K2: attention row per block + fused global stats (state mag, err std,
// gaussian mask) via last-block-done. 2048 blocks x 128 threads.
// ---------------------------------------------------------------------------
__global__ void __launch_bounds__(128) k2_attn(
    const float* __restrict__ A,
    const float* __restrict__ noiseA,
    const float* __restrict__ outputv,
    const float* __restrict__ eye,
    const float* __restrict__ stomach,
    const float* __restrict__ state,
    const int* __restrict__ stepc,
    float* __restrict__ out)
{
    int bn = blockIdx.x;
    int b  = bn >> 7;
    int n  = bn & 127;
    int m  = threadIdx.x;

    __shared__ float qs[DD];
    __shared__ float red[4];
    __shared__ float anew[NN];
    __shared__ float tpart[NN];

    float errv = 0.f, amv = 0.f;

    if (n < 2) {
        out[OFF_A + (size_t)bn * NN + m] = 0.f;
        if (m < DD) {
            float tv = (n == 0) ? eye[b * DD + m] : stomach[b * DD + m];
            out[OFF_T + bn * DD + m] = tv;
            errv = out[bn * DD + m] - tv;
            amv  = fabsf(state[bn * DD + m]);
        }
    } else {
        if (m < DD) qs[m] = g_q[bn * DD + m];
        __syncthreads();

        const float4* krow = (const float4*)(g_k + (size_t)(b * NN + m) * DD);
        float dot = 0.f;
        #pragma unroll
        for (int i = 0; i < DD / 4; i++) {
            float4 v = krow[i];
            dot += qs[4*i] * v.x + qs[4*i+1] * v.y + qs[4*i+2] * v.z + qs[4*i+3] * v.w;
        }
        float raw = dot * 0.125f + noiseA[(size_t)bn * NN + m] * 1e-5f;

        float v = wredMax(raw);
        if ((m & 31) == 0) red[m >> 5] = v;
        __syncthreads();
        float rowmax = fmaxf(fmaxf(red[0], red[1]), fmaxf(red[2], red[3]));
        __syncthreads();

        float e = expf(raw - rowmax);
        v = wredSum(e);
        if ((m & 31) == 0) red[m >> 5] = v;
        __syncthreads();
        float sum = red[0] + red[1] + red[2] + red[3];
        __syncthreads();

        float pd = e / sum;
        v = wredMax(pd);
        if ((m & 31) == 0) red[m >> 5] = v;
        __syncthreads();
        float maxpd = fmaxf(fmaxf(red[0], red[1]), fmaxf(red[2], red[3]));
        __syncthreads();

        bool keep = (pd > (1.0f / 129.0f)) || (pd == maxpd);
        float ek = keep ? e : 0.f;
        v = wredSum(ek);
        if ((m & 31) == 0) red[m >> 5] = v;
        __syncthreads();
        float sum2 = red[0] + red[1] + red[2] + red[3];
        __syncthreads();

        float P  = ek / sum2;
        float an = A[(size_t)bn * NN + m] * 0.99f + P * 0.01f;
        out[OFF_A + (size_t)bn * NN + m] = an;
        anew[m] = an;
        __syncthreads();

        // target: split 128-length mm loop over both halves of the block
        {
            int col  = m & 63;
            int half = m >> 6;           // 0 or 1
            int mm0  = half * 64;
            float acc = 0.f;
            #pragma unroll 8
            for (int mm = mm0; mm < mm0 + 64; mm++)
                acc += anew[mm] * outputv[(size_t)(b * NN + mm) * DD + col];
            tpart[m] = acc;
        }
        __syncthreads();
        if (m < DD) {
            float tv = tpart[m] + tpart[m + 64];
            out[OFF_T + bn * DD + m] = tv;
            errv = out[bn * DD + m] - tv;
            amv  = fabsf(state[bn * DD + m]);
        }
    }

    // ---- per-bn stats partials (threads >= DD contribute zeros) ----
    {
        float ae  = wredSum(errv);
        float ae2 = wredSum(errv * errv);
        float am  = wredSum(amv);
        __shared__ float se[4], se2[4], sm[4];
        int w = m >> 5;
        if ((m & 31) == 0) { se[w] = ae; se2[w] = ae2; sm[w] = am; }
        __syncthreads();
        if (m == 0) {
            g_pbn_e[bn]  = se[0] + se[1] + se[2] + se[3];
            g_pbn_e2[bn] = se2[0] + se2[1] + se2[2] + se2[3];
            g_pbn_m[bn]  = sm[0] + sm[1] + sm[2] + sm[3];
        }
    }

    // ---- last-block final reduction ----
    __shared__ int isLast;
    __syncthreads();
    if (m == 0) {
        __threadfence();
        unsigned old = atomicAdd(&g_cnt, 1u);
        isLast = (old == (unsigned)(BN - 1)) ? 1 : 0;
    }
    __syncthreads();
    if (isLast) {
        // per-b mag: 8 lanes per b, each sums 16 entries, 8-lane shuffle combine
        {
            int bb = m >> 3, j = m & 7;
            float s = 0.f;
            int base = bb * NN + j * 16;
            #pragma unroll
            for (int i = 0; i < 16; i++) s += g_pbn_m[base + i];
            #pragma unroll
            for (int o = 4; o; o >>= 1) s += __shfl_xor_sync(0xffffffffu, s, o);
            if (j == 0) g_mag[bb] = s;
        }
        // global err sums: each thread sums 16, then block reduce
        {
            float e = 0.f, e2 = 0.f;
            int base = m * 16;
            #pragma unroll
            for (int i = 0; i < 16; i++) { e += g_pbn_e[base + i]; e2 += g_pbn_e2[base + i]; }
            e = wredSum(e); e2 = wredSum(e2);
            __shared__ float r0[4], r1[4];
            int w = m >> 5;
            if ((m & 31) == 0) { r0[w] = e; r1[w] = e2; }
            __syncthreads();
            if (m == 0) {
                float E  = r0[0] + r0[1] + r0[2] + r0[3];
                float E2 = r1[0] + r1[1] + r1[2] + r1[3];
                const float M = (float)BND;
                float var = (E2 - E * E / M) / (M - 1.0f);
                g_std = sqrtf(fmaxf(var, 0.f));
                g_cnt = 0u;   // reset for next graph replay
            }
        }
        // travelling gaussian column mask
        if (m < DD) {
            float scf    = (float)(*stepc) + 1.0f;
            float center = fmodf(scf * 0.5f, 64.0f);
            float d = fabsf((float)m - center);
            d = fminf(d, 64.f - d);
            g_gmask[m] = expf(-d * d / 0.020001f);
        }
    }
}

// ---------------------------------------------------------------------------
// K4: warp per (b,n): E_curr softmax over D, Eb EMA, plasticity/mask,
// noisy_state, outer-product rms factorization -> coef, noisy.
// 256 blocks x 256 threads (8 warps each); lane handles i and i+32.
// ---------------------------------------------------------------------------
__global__ void __launch_bounds__(256) k4_coef(
    const float* __restrict__ state,
    const float* __restrict__ Ebase,
    const float* __restrict__ n1raw,
    const float* __restrict__ n2raw,
    const float* __restrict__ out)
{
    int bn   = blockIdx.x * 8 + (threadIdx.x >> 5);
    int lane = threadIdx.x & 31;
    int b    = bn >> 7;
    int g0   = bn * DD + lane;
    int g1   = g0 + 32;

    float errA = out[g0] - out[OFF_T + g0];
    float errB = out[g1] - out[OFF_T + g1];

    float mx = wredMax(fmaxf(errA, errB));
    float exA = expf(errA - mx), exB = expf(errB - mx);
    float sm = wredSum(exA + exB);
    float EcA = exA / sm, EcB = exB / sm;

    float Eb0A = Ebase[g0], Eb0B = Ebase[g1];
    float EbA = (Eb0A == 0.f) ? EcA : Eb0A;
    float EbB = (Eb0B == 0.f) ? EcB : Eb0B;
    EbA = EbA * 0.95f + 0.05f * EcA;
    EbB = EbB * 0.95f + 0.05f * EcB;
    float advA = EcA - EbA, advB = EcB - EbB;
    float plA = 1.f + advA * rsqrtf(advA * advA + 1e-6f);
    float plB = 1.f + advB * rsqrtf(advB * advB + 1e-6f);
    float mkA = (EbA > 0.f) ? 1.f : 0.f;
    float mkB = (EbB > 0.f) ? 1.f : 0.f;

    float inv_mag = 1.f / (1.f + g_mag[b]);
    float sd = g_std * 0.8f;
    float nsA = state[g0] + n1raw[g0] * inv_mag + n2raw[g0] * sd;
    float nsB = state[g1] + n1raw[g1] * inv_mag + n2raw[g1] * sd;

    float se2 = wredSum(errA * errA + errB * errB);
    float sn2 = wredSum(nsA * nsA + nsB * nsB);
    float rn = rsqrtf((se2 * (1.f / DD)) * (sn2 * (1.f / DD)) + 1e-6f);

    g_coef[g0]  = -errA * rn * plA * mkA;
    g_coef[g1]  = -errB * rn * plB * mkB;
    g_noisy[g0] = nsA;
    g_noisy[g1] = nsB;
}

// ---------------------------------------------------------------------------
// K5: fused grads + momentum + gaussian column mask + W update + row rms.
// 16 threads per row (float4 each), 16 rows per 256-thread block.
// M loads streaming (__ldcs), W-new stores streaming (__stcs); W loads keep
// default policy to exploit L2 residency from k1.
// ---------------------------------------------------------------------------
__device__ __forceinline__ float newW(float w, float wlat, float m, float h, float g) {
    float grad = h + 0.01f * wlat - 0.01f * w;     // LAT_DECAY*W_lat - WD*W_self
    return w + 0.0033f * (m * 0.4f + 0.6f * grad * g);
}

__global__ void __launch_bounds__(256, 7) k5_update(
    const float* __restrict__ W1, const float* __restrict__ W2, const float* __restrict__ W3,
    const float* __restrict__ M1, const float* __restrict__ M2, const float* __restrict__ M3,
    float* __restrict__ out)
{
    int t   = threadIdx.x;
    int tx  = t & 15;
    int row = blockIdx.x * 16 + (t >> 4);  // 0..BND-1  (b,n,i)
    int bn  = row >> 6;
    size_t b4 = (size_t)row * 16 + tx;     // float4 index into (BND x D) matrices

    float4 w1 = ((const float4*)W1)[b4];
    float4 w2 = ((const float4*)W2)[b4];
    float4 w3 = ((const float4*)W3)[b4];

    float  c  = g_coef[row];
    float4 ns = ((const float4*)g_noisy)[bn * 16 + tx];
    float4 gm = ((const float4*)g_gmask)[tx];
    float4 h  = { c * ns.x, c * ns.y, c * ns.z, c * ns.w };

    // --- W1 update ---
    {
        float4 m1 = __ldcs(((const float4*)M1) + b4);
        float4 t1;
        t1.x = newW(w1.x, w3.x, m1.x, h.x, gm.x);
        t1.y = newW(w1.y, w3.y, m1.y, h.y, gm.y);
        t1.z = newW(w1.z, w3.z, m1.z, h.z, gm.z);
        t1.w = newW(w1.w, w3.w, m1.w, h.w, gm.w);
        float s1 = t1.x*t1.x + t1.y*t1.y + t1.z*t1.z + t1.w*t1.w;
        #pragma unroll
        for (int o = 8; o; o >>= 1) s1 += __shfl_xor_sync(0xffffffffu, s1, o);
        float r1 = rsqrtf(s1 * (1.f / 64.f) + 1e-6f);
        float4 o1 = { t1.x*r1, t1.y*r1, t1.z*r1, t1.w*r1 };
        __stcs(((float4*)(out + OFF_W1)) + b4, o1);
    }
    // --- W2 update ---
    {
        float4 m2 = __ldcs(((const float4*)M2) + b4);
        float4 t2;
        t2.x = newW(w2.x, w1.x, m2.x, h.x, gm.x);
        t2.y = newW(w2.y, w1.y, m2.y, h.y, gm.y);
        t2.z = newW(w2.z, w1.z, m2.z, h.z, gm.z);
        t2.w = newW(w2.w, w1.w, m2.w, h.w, gm.w);
        float s2 = t2.x*t2.x + t2.y*t2.y + t2.z*t2.z + t2.w*t2.w;
        #pragma unroll
        for (int o = 8; o; o >>= 1) s2 += __shfl_xor_sync(0xffffffffu, s2, o);
        float r2 = rsqrtf(s2 * (1.f / 64.f) + 1e-6f);
        float4 o2 = { t2.x*r2, t2.y*r2, t2.z*r2, t2.w*r2 };
        __stcs(((float4*)(out + OFF_W2)) + b4, o2);
    }
    // --- W3 update ---
    {
        float4 m3 = __ldcs(((const float4*)M3) + b4);
        float4 t3;
        t3.x = newW(w3.x, w2.x, m3.x, h.x, gm.x);
        t3.y = newW(w3.y, w2.y, m3.y, h.y, gm.y);
        t3.z = newW(w3.z, w2.z, m3.z, h.z, gm.z);
        t3.w = newW(w3.w, w2.w, m3.w, h.w, gm.w);
        float s3 = t3.x*t3.x + t3.y*t3.y + t3.z*t3.z + t3.w*t3.w;
        #pragma unroll
        for (int o = 8; o; o >>= 1) s3 += __shfl_xor_sync(0xffffffffu, s3, o);
        float r3 = rsqrtf(s3 * (1.f / 64.f) + 1e-6f);
        float4 o3 = { t3.x*r3, t3.y*r3, t3.z*r3, t3.w*r3 };
        __stcs(((float4*)(out + OFF_W3)) + b4, o3);
    }
}

// ---------------------------------------------------------------------------
extern "C" void kernel_launch(void* const* d_in, const int* in_sizes, int n_in,
                              void* d_out, int out_size)
{
    const float* eye     = (const float*)d_in[0];
    const float* stomach = (const float*)d_in[1];
    const float* state   = (const float*)d_in[2];
    const float* outputv = (const float*)d_in[3];
    const float* W1      = (const float*)d_in[4];
    const float* W2      = (const float*)d_in[5];
    const float* W3      = (const float*)d_in[6];
    const float* M1      = (const float*)d_in[7];
    const float* M2      = (const float*)d_in[8];
    const float* M3      = (const float*)d_in[9];
    const float* Ebase   = (const float*)d_in[10];
    const float* A       = (const float*)d_in[11];
    const float* noiseA  = (const float*)d_in[12];
    const float* n1raw   = (const float*)d_in[13];
    const float* n2raw   = (const float*)d_in[14];
    const int*   stepc   = (const int*)d_in[15];
    float* out = (float*)d_out;

    k1_qkp<<<BN, 192>>>(state, W1, W2, W3, out);
    k2_attn<<<BN, 128>>>(A, noiseA, outputv, eye, stomach, state, stepc, out);
    k4_coef<<<BN / 8, 256>>>(state, Ebase, n1raw, n2raw, out);
    k5_update<<<BND / 16, 256>>>(W1, W2, W3, M1, M2, M3, out);
}

// round 6
// speedup vs baseline: 1.2134x; 1.0436x over previous
#include <cuda_runtime.h>
#include <math.h>

#define BB 16
#define NN 128
#define DD 64
#define BN  2048        // BB*NN
#define BND 131072      // BN*DD
#define BNDD 8388608    // BND*DD

// out layout: prediction[BND], target[BND], A_new[BN*NN], W1n[BNDD], W2n[BNDD], W3n[BNDD]
#define OFF_T  (BND)
#define OFF_A  (2*BND)
#define OFF_W1 (4*BND)            // 2*BND + BN*NN = 4*BND
#define OFF_W2 (OFF_W1 + BNDD)
#define OFF_W3 (OFF_W2 + BNDD)

// scratch (static device globals; no allocation)
__device__ float g_q[BND];
__device__ float g_k[BND];
__device__ float g_coef[BND];
__device__ float g_noisy[BND];
__device__ float g_pbn_m[BN];
__device__ float g_pbn_e[BN];
__device__ float g_pbn_e2[BN];
__device__ float g_mag[BB];
__device__ float g_gmask[DD];
__device__ float g_std;
__device__ unsigned g_cnt = 0;

__device__ __forceinline__ float wredMax(float v) {
    #pragma unroll
    for (int o = 16; o; o >>= 1) v = fmaxf(v, __shfl_xor_sync(0xffffffffu, v, o));
    return v;
}
__device__ __forceinline__ float wredSum(float v) {
    #pragma unroll
    for (int o = 16; o; o >>= 1) v += __shfl_xor_sync(0xffffffffu, v, o);
    return v;
}

// ---------------------------------------------------------------------------
// K1: per (b,n) three matvecs: raw_pred = state@W1, k = state@W2, q = state@W3
// plus prediction elementwise. Vectorized: 16 threads x float4 per matvec,
// 4 bn per 192-thread block -> 512 blocks, LDG.128 throughout.
// ---------------------------------------------------------------------------
__global__ void __launch_bounds__(192) k1_qkp(
    const float* __restrict__ state,
    const float* __restrict__ W1, const float* __restrict__ W2, const float* __restrict__ W3,
    float* __restrict__ out)
{
    int t   = threadIdx.x;
    int sub = t / 48;         // 0..3 : bn within block
    int r   = t % 48;
    int x   = r >> 4;         // 0: W1(pred), 1: W2(k), 2: W3(q)
    int kk  = r & 15;         // float4 column group
    int bn  = blockIdx.x * 4 + sub;

    __shared__ float s[4][DD];
    for (int i = t; i < 4 * DD; i += 192)
        s[i >> 6][i & 63] = state[blockIdx.x * 4 * DD + i];
    __syncthreads();

    const float* Wp = (x == 0) ? W1 : ((x == 1) ? W2 : W3);
    const float4* Wb = (const float4*)(Wp + (size_t)bn * DD * DD) + kk;

    float4 acc = {0.f, 0.f, 0.f, 0.f};
    #pragma unroll
    for (int j = 0; j < DD; j++) {
        float  sv = s[sub][j];
        float4 w  = Wb[j * 16];
        acc.x += sv * w.x; acc.y += sv * w.y;
        acc.z += sv * w.z; acc.w += sv * w.w;
    }

    if (x == 0) {
        const float C = 1.8477590650225735f;  // sqrt(2+sqrt(2))
        float4 p;
        p.x = tanhf(acc.x - tanhf(acc.x) * 0.6f) * C;
        p.y = tanhf(acc.y - tanhf(acc.y) * 0.6f) * C;
        p.z = tanhf(acc.z - tanhf(acc.z) * 0.6f) * C;
        p.w = tanhf(acc.w - tanhf(acc.w) * 0.6f) * C;
        ((float4*)out)[bn * 16 + kk] = p;
    } else if (x == 1) {
        ((float4*)g_k)[bn * 16 + kk] = acc;
    } else {
        ((float4*)g_q)[bn * 16 + kk] = acc;
    }
}

// ---------------------------------------------------------------------------
// K2: attention row per block + fused global stats (state mag, err std,
// gaussian mask) via last-block-done. 2048 blocks x 128 threads.
// maxpd reduction eliminated: max(e) == 1.0f exactly => maxpd = 1/sum.
// ---------------------------------------------------------------------------
__global__ void __launch_bounds__(128) k2_attn(
    const float* __restrict__ A,
    const float* __restrict__ noiseA,
    const float* __restrict__ outputv,
    const float* __restrict__ eye,
    const float* __restrict__ stomach,
    const float* __restrict__ state,
    const int* __restrict__ stepc,
    float* __restrict__ out)
{
    int bn = blockIdx.x;
    int b  = bn >> 7;
    int n  = bn & 127;
    int m  = threadIdx.x;

    __shared__ float qs[DD];
    __shared__ float red[4];
    __shared__ float anew[NN];
    __shared__ float tpart[NN];

    float errv = 0.f, amv = 0.f;

    if (n < 2) {
        out[OFF_A + (size_t)bn * NN + m] = 0.f;
        if (m < DD) {
            float tv = (n == 0) ? eye[b * DD + m] : stomach[b * DD + m];
            out[OFF_T + bn * DD + m] = tv;
            errv = out[bn * DD + m] - tv;
            amv  = fabsf(state[bn * DD + m]);
        }
    } else {
        if (m < DD) qs[m] = g_q[bn * DD + m];
        __syncthreads();

        const float4* krow = (const float4*)(g_k + (size_t)(b * NN + m) * DD);
        float dot = 0.f;
        #pragma unroll
        for (int i = 0; i < DD / 4; i++) {
            float4 v = krow[i];
            dot += qs[4*i] * v.x + qs[4*i+1] * v.y + qs[4*i+2] * v.z + qs[4*i+3] * v.w;
        }
        float raw = dot * 0.125f + noiseA[(size_t)bn * NN + m] * 1e-5f;

        float v = wredMax(raw);
        if ((m & 31) == 0) red[m >> 5] = v;
        __syncthreads();
        float rowmax = fmaxf(fmaxf(red[0], red[1]), fmaxf(red[2], red[3]));
        __syncthreads();

        float e = expf(raw - rowmax);      // max element: e == 1.0f exactly
        v = wredSum(e);
        if ((m & 31) == 0) red[m >> 5] = v;
        __syncthreads();
        float sum = red[0] + red[1] + red[2] + red[3];
        __syncthreads();

        float pd    = e / sum;
        float maxpd = 1.0f / sum;          // == max(pd) bit-exactly

        bool keep = (pd > (1.0f / 129.0f)) || (pd == maxpd);
        float ek = keep ? e : 0.f;
        v = wredSum(ek);
        if ((m & 31) == 0) red[m >> 5] = v;
        __syncthreads();
        float sum2 = red[0] + red[1] + red[2] + red[3];
        __syncthreads();

        float P  = ek / sum2;
        float an = A[(size_t)bn * NN + m] * 0.99f + P * 0.01f;
        out[OFF_A + (size_t)bn * NN + m] = an;
        anew[m] = an;
        __syncthreads();

        // target: split 128-length mm loop over both halves of the block
        {
            int col  = m & 63;
            int half = m >> 6;           // 0 or 1
            int mm0  = half * 64;
            float acc = 0.f;
            #pragma unroll 8
            for (int mm = mm0; mm < mm0 + 64; mm++)
                acc += anew[mm] * outputv[(size_t)(b * NN + mm) * DD + col];
            tpart[m] = acc;
        }
        __syncthreads();
        if (m < DD) {
            float tv = tpart[m] + tpart[m + 64];
            out[OFF_T + bn * DD + m] = tv;
            errv = out[bn * DD + m] - tv;
            amv  = fabsf(state[bn * DD + m]);
        }
    }

    // ---- per-bn stats partials (threads >= DD contribute zeros) ----
    {
        float ae  = wredSum(errv);
        float ae2 = wredSum(errv * errv);
        float am  = wredSum(amv);
        __shared__ float se[4], se2[4], sm[4];
        int w = m >> 5;
        if ((m & 31) == 0) { se[w] = ae; se2[w] = ae2; sm[w] = am; }
        __syncthreads();
        if (m == 0) {
            g_pbn_e[bn]  = se[0] + se[1] + se[2] + se[3];
            g_pbn_e2[bn] = se2[0] + se2[1] + se2[2] + se2[3];
            g_pbn_m[bn]  = sm[0] + sm[1] + sm[2] + sm[3];
        }
    }

    // ---- last-block final reduction ----
    __shared__ int isLast;
    __syncthreads();
    if (m == 0) {
        __threadfence();
        unsigned old = atomicAdd(&g_cnt, 1u);
        isLast = (old == (unsigned)(BN - 1)) ? 1 : 0;
    }
    __syncthreads();
    if (isLast) {
        // per-b mag: 8 lanes per b, each sums 16 entries, 8-lane shuffle combine
        {
            int bb = m >> 3, j = m & 7;
            float s = 0.f;
            int base = bb * NN + j * 16;
            #pragma unroll
            for (int i = 0; i < 16; i++) s += g_pbn_m[base + i];
            #pragma unroll
            for (int o = 4; o; o >>= 1) s += __shfl_xor_sync(0xffffffffu, s, o);
            if (j == 0) g_mag[bb] = s;
        }
        // global err sums: each thread sums 16, then block reduce
        {
            float e = 0.f, e2 = 0.f;
            int base = m * 16;
            #pragma unroll
            for (int i = 0; i < 16; i++) { e += g_pbn_e[base + i]; e2 += g_pbn_e2[base + i]; }
            e = wredSum(e); e2 = wredSum(e2);
            __shared__ float r0[4], r1[4];
            int w = m >> 5;
            if ((m & 31) == 0) { r0[w] = e; r1[w] = e2; }
            __syncthreads();
            if (m == 0) {
                float E  = r0[0] + r0[1] + r0[2] + r0[3];
                float E2 = r1[0] + r1[1] + r1[2] + r1[3];
                const float M = (float)BND;
                float var = (E2 - E * E / M) / (M - 1.0f);
                g_std = sqrtf(fmaxf(var, 0.f));
                g_cnt = 0u;   // reset for next graph replay
            }
        }
        // travelling gaussian column mask
        if (m < DD) {
            float scf    = (float)(*stepc) + 1.0f;
            float center = fmodf(scf * 0.5f, 64.0f);
            float d = fabsf((float)m - center);
            d = fminf(d, 64.f - d);
            g_gmask[m] = expf(-d * d / 0.020001f);
        }
    }
}

// ---------------------------------------------------------------------------
// K4: warp per (b,n): E_curr softmax over D, Eb EMA, plasticity/mask,
// noisy_state, outer-product rms factorization -> coef, noisy.
// 256 blocks x 256 threads (8 warps each); lane handles i and i+32.
// ---------------------------------------------------------------------------
__global__ void __launch_bounds__(256) k4_coef(
    const float* __restrict__ state,
    const float* __restrict__ Ebase,
    const float* __restrict__ n1raw,
    const float* __restrict__ n2raw,
    const float* __restrict__ out)
{
    int bn   = blockIdx.x * 8 + (threadIdx.x >> 5);
    int lane = threadIdx.x & 31;
    int b    = bn >> 7;
    int g0   = bn * DD + lane;
    int g1   = g0 + 32;

    float errA = out[g0] - out[OFF_T + g0];
    float errB = out[g1] - out[OFF_T + g1];

    float mx = wredMax(fmaxf(errA, errB));
    float exA = expf(errA - mx), exB = expf(errB - mx);
    float sm = wredSum(exA + exB);
    float EcA = exA / sm, EcB = exB / sm;

    float Eb0A = Ebase[g0], Eb0B = Ebase[g1];
    float EbA = (Eb0A == 0.f) ? EcA : Eb0A;
    float EbB = (Eb0B == 0.f) ? EcB : Eb0B;
    EbA = EbA * 0.95f + 0.05f * EcA;
    EbB = EbB * 0.95f + 0.05f * EcB;
    float advA = EcA - EbA, advB = EcB - EbB;
    float plA = 1.f + advA * rsqrtf(advA * advA + 1e-6f);
    float plB = 1.f + advB * rsqrtf(advB * advB + 1e-6f);
    float mkA = (EbA > 0.f) ? 1.f : 0.f;
    float mkB = (EbB > 0.f) ? 1.f : 0.f;

    float inv_mag = 1.f / (1.f + g_mag[b]);
    float sd = g_std * 0.8f;
    float nsA = state[g0] + n1raw[g0] * inv_mag + n2raw[g0] * sd;
    float nsB = state[g1] + n1raw[g1] * inv_mag + n2raw[g1] * sd;

    float se2 = wredSum(errA * errA + errB * errB);
    float sn2 = wredSum(nsA * nsA + nsB * nsB);
    float rn = rsqrtf((se2 * (1.f / DD)) * (sn2 * (1.f / DD)) + 1e-6f);

    g_coef[g0]  = -errA * rn * plA * mkA;
    g_coef[g1]  = -errB * rn * plB * mkB;
    g_noisy[g0] = nsA;
    g_noisy[g1] = nsB;
}

// ---------------------------------------------------------------------------
// K5: fused grads + momentum + gaussian column mask + W update + row rms.
// 16 threads per row (float4 each), 16 rows per 256-thread block.
// Block order REVERSED so first-scheduled blocks touch the W region most
// recently streamed by k1 (LRU-friendly). M loads streaming (__ldcs),
// W-new stores streaming (__stcs); W loads default policy for L2 reuse.
// ---------------------------------------------------------------------------
__device__ __forceinline__ float newW(float w, float wlat, float m, float h, float g) {
    float grad = h + 0.01f * wlat - 0.01f * w;     // LAT_DECAY*W_lat - WD*W_self
    return w + 0.0033f * (m * 0.4f + 0.6f * grad * g);
}

__global__ void __launch_bounds__(256, 7) k5_update(
    const float* __restrict__ W1, const float* __restrict__ W2, const float* __restrict__ W3,
    const float* __restrict__ M1, const float* __restrict__ M2, const float* __restrict__ M3,
    float* __restrict__ out)
{
    int t   = threadIdx.x;
    int tx  = t & 15;
    int blk = (int)gridDim.x - 1 - (int)blockIdx.x;   // reversed walk
    int row = blk * 16 + (t >> 4);         // 0..BND-1  (b,n,i)
    int bn  = row >> 6;
    size_t b4 = (size_t)row * 16 + tx;     // float4 index into (BND x D) matrices

    float4 w1 = ((const float4*)W1)[b4];
    float4 w2 = ((const float4*)W2)[b4];
    float4 w3 = ((const float4*)W3)[b4];

    float  c  = g_coef[row];
    float4 ns = ((const float4*)g_noisy)[bn * 16 + tx];
    float4 gm = ((const float4*)g_gmask)[tx];
    float4 h  = { c * ns.x, c * ns.y, c * ns.z, c * ns.w };

    // --- W1 update ---
    {
        float4 m1 = __ldcs(((const float4*)M1) + b4);
        float4 t1;
        t1.x = newW(w1.x, w3.x, m1.x, h.x, gm.x);
        t1.y = newW(w1.y, w3.y, m1.y, h.y, gm.y);
        t1.z = newW(w1.z, w3.z, m1.z, h.z, gm.z);
        t1.w = newW(w1.w, w3.w, m1.w, h.w, gm.w);
        float s1 = t1.x*t1.x + t1.y*t1.y + t1.z*t1.z + t1.w*t1.w;
        #pragma unroll
        for (int o = 8; o; o >>= 1) s1 += __shfl_xor_sync(0xffffffffu, s1, o);
        float r1 = rsqrtf(s1 * (1.f / 64.f) + 1e-6f);
        float4 o1 = { t1.x*r1, t1.y*r1, t1.z*r1, t1.w*r1 };
        __stcs(((float4*)(out + OFF_W1)) + b4, o1);
    }
    // --- W2 update ---
    {
        float4 m2 = __ldcs(((const float4*)M2) + b4);
        float4 t2;
        t2.x = newW(w2.x, w1.x, m2.x, h.x, gm.x);
        t2.y = newW(w2.y, w1.y, m2.y, h.y, gm.y);
        t2.z = newW(w2.z, w1.z, m2.z, h.z, gm.z);
        t2.w = newW(w2.w, w1.w, m2.w, h.w, gm.w);
        float s2 = t2.x*t2.x + t2.y*t2.y + t2.z*t2.z + t2.w*t2.w;
        #pragma unroll
        for (int o = 8; o; o >>= 1) s2 += __shfl_xor_sync(0xffffffffu, s2, o);
        float r2 = rsqrtf(s2 * (1.f / 64.f) + 1e-6f);
        float4 o2 = { t2.x*r2, t2.y*r2, t2.z*r2, t2.w*r2 };
        __stcs(((float4*)(out + OFF_W2)) + b4, o2);
    }
    // --- W3 update ---
    {
        float4 m3 = __ldcs(((const float4*)M3) + b4);
        float4 t3;
        t3.x = newW(w3.x, w2.x, m3.x, h.x, gm.x);
        t3.y = newW(w3.y, w2.y, m3.y, h.y, gm.y);
        t3.z = newW(w3.z, w2.z, m3.z, h.z, gm.z);
        t3.w = newW(w3.w, w2.w, m3.w, h.w, gm.w);
        float s3 = t3.x*t3.x + t3.y*t3.y + t3.z*t3.z + t3.w*t3.w;
        #pragma unroll
        for (int o = 8; o; o >>= 1) s3 += __shfl_xor_sync(0xffffffffu, s3, o);
        float r3 = rsqrtf(s3 * (1.f / 64.f) + 1e-6f);
        float4 o3 = { t3.x*r3, t3.y*r3, t3.z*r3, t3.w*r3 };
        __stcs(((float4*)(out + OFF_W3)) + b4, o3);
    }
}

// ---------------------------------------------------------------------------
extern "C" void kernel_launch(void* const* d_in, const int* in_sizes, int n_in,
                              void* d_out, int out_size)
{
    const float* eye     = (const float*)d_in[0];
    const float* stomach = (const float*)d_in[1];
    const float* state   = (const float*)d_in[2];
    const float* outputv = (const float*)d_in[3];
    const float* W1      = (const float*)d_in[4];
    const float* W2      = (const float*)d_in[5];
    const float* W3      = (const float*)d_in[6];
    const float* M1      = (const float*)d_in[7];
    const float* M2      = (const float*)d_in[8];
    const float* M3      = (const float*)d_in[9];
    const float* Ebase   = (const float*)d_in[10];
    const float* A       = (const float*)d_in[11];
    const float* noiseA  = (const float*)d_in[12];
    const float* n1raw   = (const float*)d_in[13];
    const float* n2raw   = (const float*)d_in[14];
    const int*   stepc   = (const int*)d_in[15];
    float* out = (float*)d_out;

    k1_qkp<<<BN / 4, 192>>>(state, W1, W2, W3, out);
    k2_attn<<<BN, 128>>>(A, noiseA, outputv, eye, stomach, state, stepc, out);
    k4_coef<<<BN / 8, 256>>>(state, Ebase, n1raw, n2raw, out);
    k5_update<<<BND / 16, 256>>>(W1, W2, W3, M1, M2, M3, out);
}

// round 7
// speedup vs baseline: 1.2380x; 1.0202x over previous
#include <cuda_runtime.h>
#include <math.h>

#define BB 16
#define NN 128
#define DD 64
#define BN  2048        // BB*NN
#define BND 131072      // BN*DD
#define BNDD 8388608    // BND*DD

// out layout: prediction[BND], target[BND], A_new[BN*NN], W1n[BNDD], W2n[BNDD], W3n[BNDD]
#define OFF_T  (BND)
#define OFF_A  (2*BND)
#define OFF_W1 (4*BND)            // 2*BND + BN*NN = 4*BND
#define OFF_W2 (OFF_W1 + BNDD)
#define OFF_W3 (OFF_W2 + BNDD)

// scratch (static device globals; no allocation)
__device__ float g_q[BND];
__device__ float g_k[BND];
__device__ float g_coef[BND];
__device__ float g_noisy[BND];
__device__ float g_pbn_m[BN];
__device__ float g_pbn_e[BN];
__device__ float g_pbn_e2[BN];
__device__ float g_mag[BB];
__device__ float g_gmask[DD];
__device__ float g_std;
__device__ unsigned g_cnt = 0;

__device__ __forceinline__ float wredMax(float v) {
    #pragma unroll
    for (int o = 16; o; o >>= 1) v = fmaxf(v, __shfl_xor_sync(0xffffffffu, v, o));
    return v;
}
__device__ __forceinline__ float wredSum(float v) {
    #pragma unroll
    for (int o = 16; o; o >>= 1) v += __shfl_xor_sync(0xffffffffu, v, o);
    return v;
}

// ---------------------------------------------------------------------------
// K1: per (b,n) three matvecs: raw_pred = state@W1, k = state@W2, q = state@W3
// plus prediction elementwise. Vectorized: 16 threads x float4 per matvec,
// 4 bn per 192-thread block -> 512 blocks, LDG.128 throughout.
// unroll bounded to 8 + min-blocks 6 to prevent register spill / occupancy
// collapse from full 64-deep unroll.
// ---------------------------------------------------------------------------
__global__ void __launch_bounds__(192, 6) k1_qkp(
    const float* __restrict__ state,
    const float* __restrict__ W1, const float* __restrict__ W2, const float* __restrict__ W3,
    float* __restrict__ out)
{
    int t   = threadIdx.x;
    int sub = t / 48;         // 0..3 : bn within block
    int r   = t % 48;
    int x   = r >> 4;         // 0: W1(pred), 1: W2(k), 2: W3(q)
    int kk  = r & 15;         // float4 column group
    int bn  = blockIdx.x * 4 + sub;

    __shared__ float s[4][DD];
    for (int i = t; i < 4 * DD; i += 192)
        s[i >> 6][i & 63] = state[blockIdx.x * 4 * DD + i];
    __syncthreads();

    const float* Wp = (x == 0) ? W1 : ((x == 1) ? W2 : W3);
    const float4* Wb = (const float4*)(Wp + (size_t)bn * DD * DD) + kk;

    float4 acc = {0.f, 0.f, 0.f, 0.f};
    #pragma unroll 8
    for (int j = 0; j < DD; j++) {
        float  sv = s[sub][j];
        float4 w  = Wb[j * 16];
        acc.x += sv * w.x; acc.y += sv * w.y;
        acc.z += sv * w.z; acc.w += sv * w.w;
    }

    if (x == 0) {
        const float C = 1.8477590650225735f;  // sqrt(2+sqrt(2))
        float4 p;
        p.x = tanhf(acc.x - tanhf(acc.x) * 0.6f) * C;
        p.y = tanhf(acc.y - tanhf(acc.y) * 0.6f) * C;
        p.z = tanhf(acc.z - tanhf(acc.z) * 0.6f) * C;
        p.w = tanhf(acc.w - tanhf(acc.w) * 0.6f) * C;
        ((float4*)out)[bn * 16 + kk] = p;
    } else if (x == 1) {
        ((float4*)g_k)[bn * 16 + kk] = acc;
    } else {
        ((float4*)g_q)[bn * 16 + kk] = acc;
    }
}

// ---------------------------------------------------------------------------
// K2: attention row per block + fused global stats (state mag, err std,
// gaussian mask) via last-block-done. 2048 blocks x 128 threads.
// maxpd reduction eliminated: max(e) == 1.0f exactly => maxpd = 1/sum.
// ---------------------------------------------------------------------------
__global__ void __launch_bounds__(128) k2_attn(
    const float* __restrict__ A,
    const float* __restrict__ noiseA,
    const float* __restrict__ outputv,
    const float* __restrict__ eye,
    const float* __restrict__ stomach,
    const float* __restrict__ state,
    const int* __restrict__ stepc,
    float* __restrict__ out)
{
    int bn = blockIdx.x;
    int b  = bn >> 7;
    int n  = bn & 127;
    int m  = threadIdx.x;

    __shared__ float qs[DD];
    __shared__ float red[4];
    __shared__ float anew[NN];
    __shared__ float tpart[NN];

    float errv = 0.f, amv = 0.f;

    if (n < 2) {
        out[OFF_A + (size_t)bn * NN + m] = 0.f;
        if (m < DD) {
            float tv = (n == 0) ? eye[b * DD + m] : stomach[b * DD + m];
            out[OFF_T + bn * DD + m] = tv;
            errv = out[bn * DD + m] - tv;
            amv  = fabsf(state[bn * DD + m]);
        }
    } else {
        if (m < DD) qs[m] = g_q[bn * DD + m];
        __syncthreads();

        const float4* krow = (const float4*)(g_k + (size_t)(b * NN + m) * DD);
        float dot = 0.f;
        #pragma unroll
        for (int i = 0; i < DD / 4; i++) {
            float4 v = krow[i];
            dot += qs[4*i] * v.x + qs[4*i+1] * v.y + qs[4*i+2] * v.z + qs[4*i+3] * v.w;
        }
        float raw = dot * 0.125f + noiseA[(size_t)bn * NN + m] * 1e-5f;

        float v = wredMax(raw);
        if ((m & 31) == 0) red[m >> 5] = v;
        __syncthreads();
        float rowmax = fmaxf(fmaxf(red[0], red[1]), fmaxf(red[2], red[3]));
        __syncthreads();

        float e = expf(raw - rowmax);      // max element: e == 1.0f exactly
        v = wredSum(e);
        if ((m & 31) == 0) red[m >> 5] = v;
        __syncthreads();
        float sum = red[0] + red[1] + red[2] + red[3];
        __syncthreads();

        float pd    = e / sum;
        float maxpd = 1.0f / sum;          // == max(pd) bit-exactly

        bool keep = (pd > (1.0f / 129.0f)) || (pd == maxpd);
        float ek = keep ? e : 0.f;
        v = wredSum(ek);
        if ((m & 31) == 0) red[m >> 5] = v;
        __syncthreads();
        float sum2 = red[0] + red[1] + red[2] + red[3];
        __syncthreads();

        float P  = ek / sum2;
        float an = A[(size_t)bn * NN + m] * 0.99f + P * 0.01f;
        out[OFF_A + (size_t)bn * NN + m] = an;
        anew[m] = an;
        __syncthreads();

        // target: split 128-length mm loop over both halves of the block
        {
            int col  = m & 63;
            int half = m >> 6;           // 0 or 1
            int mm0  = half * 64;
            float acc = 0.f;
            #pragma unroll 8
            for (int mm = mm0; mm < mm0 + 64; mm++)
                acc += anew[mm] * outputv[(size_t)(b * NN + mm) * DD + col];
            tpart[m] = acc;
        }
        __syncthreads();
        if (m < DD) {
            float tv = tpart[m] + tpart[m + 64];
            out[OFF_T + bn * DD + m] = tv;
            errv = out[bn * DD + m] - tv;
            amv  = fabsf(state[bn * DD + m]);
        }
    }

    // ---- per-bn stats partials (threads >= DD contribute zeros) ----
    {
        float ae  = wredSum(errv);
        float ae2 = wredSum(errv * errv);
        float am  = wredSum(amv);
        __shared__ float se[4], se2[4], sm[4];
        int w = m >> 5;
        if ((m & 31) == 0) { se[w] = ae; se2[w] = ae2; sm[w] = am; }
        __syncthreads();
        if (m == 0) {
            g_pbn_e[bn]  = se[0] + se[1] + se[2] + se[3];
            g_pbn_e2[bn] = se2[0] + se2[1] + se2[2] + se2[3];
            g_pbn_m[bn]  = sm[0] + sm[1] + sm[2] + sm[3];
        }
    }

    // ---- last-block final reduction ----
    __shared__ int isLast;
    __syncthreads();
    if (m == 0) {
        __threadfence();
        unsigned old = atomicAdd(&g_cnt, 1u);
        isLast = (old == (unsigned)(BN - 1)) ? 1 : 0;
    }
    __syncthreads();
    if (isLast) {
        // per-b mag: 8 lanes per b, each sums 16 entries, 8-lane shuffle combine
        {
            int bb = m >> 3, j = m & 7;
            float s = 0.f;
            int base = bb * NN + j * 16;
            #pragma unroll
            for (int i = 0; i < 16; i++) s += g_pbn_m[base + i];
            #pragma unroll
            for (int o = 4; o; o >>= 1) s += __shfl_xor_sync(0xffffffffu, s, o);
            if (j == 0) g_mag[bb] = s;
        }
        // global err sums: each thread sums 16, then block reduce
        {
            float e = 0.f, e2 = 0.f;
            int base = m * 16;
            #pragma unroll
            for (int i = 0; i < 16; i++) { e += g_pbn_e[base + i]; e2 += g_pbn_e2[base + i]; }
            e = wredSum(e); e2 = wredSum(e2);
            __shared__ float r0[4], r1[4];
            int w = m >> 5;
            if ((m & 31) == 0) { r0[w] = e; r1[w] = e2; }
            __syncthreads();
            if (m == 0) {
                float E  = r0[0] + r0[1] + r0[2] + r0[3];
                float E2 = r1[0] + r1[1] + r1[2] + r1[3];
                const float M = (float)BND;
                float var = (E2 - E * E / M) / (M - 1.0f);
                g_std = sqrtf(fmaxf(var, 0.f));
                g_cnt = 0u;   // reset for next graph replay
            }
        }
        // travelling gaussian column mask
        if (m < DD) {
            float scf    = (float)(*stepc) + 1.0f;
            float center = fmodf(scf * 0.5f, 64.0f);
            float d = fabsf((float)m - center);
            d = fminf(d, 64.f - d);
            g_gmask[m] = expf(-d * d / 0.020001f);
        }
    }
}

// ---------------------------------------------------------------------------
// K4: warp per (b,n): E_curr softmax over D, Eb EMA, plasticity/mask,
// noisy_state, outer-product rms factorization -> coef, noisy.
// 256 blocks x 256 threads (8 warps each); lane handles i and i+32.
// ---------------------------------------------------------------------------
__global__ void __launch_bounds__(256) k4_coef(
    const float* __restrict__ state,
    const float* __restrict__ Ebase,
    const float* __restrict__ n1raw,
    const float* __restrict__ n2raw,
    const float* __restrict__ out)
{
    int bn   = blockIdx.x * 8 + (threadIdx.x >> 5);
    int lane = threadIdx.x & 31;
    int b    = bn >> 7;
    int g0   = bn * DD + lane;
    int g1   = g0 + 32;

    float errA = out[g0] - out[OFF_T + g0];
    float errB = out[g1] - out[OFF_T + g1];

    float mx = wredMax(fmaxf(errA, errB));
    float exA = expf(errA - mx), exB = expf(errB - mx);
    float sm = wredSum(exA + exB);
    float EcA = exA / sm, EcB = exB / sm;

    float Eb0A = Ebase[g0], Eb0B = Ebase[g1];
    float EbA = (Eb0A == 0.f) ? EcA : Eb0A;
    float EbB = (Eb0B == 0.f) ? EcB : Eb0B;
    EbA = EbA * 0.95f + 0.05f * EcA;
    EbB = EbB * 0.95f + 0.05f * EcB;
    float advA = EcA - EbA, advB = EcB - EbB;
    float plA = 1.f + advA * rsqrtf(advA * advA + 1e-6f);
    float plB = 1.f + advB * rsqrtf(advB * advB + 1e-6f);
    float mkA = (EbA > 0.f) ? 1.f : 0.f;
    float mkB = (EbB > 0.f) ? 1.f : 0.f;

    float inv_mag = 1.f / (1.f + g_mag[b]);
    float sd = g_std * 0.8f;
    float nsA = state[g0] + n1raw[g0] * inv_mag + n2raw[g0] * sd;
    float nsB = state[g1] + n1raw[g1] * inv_mag + n2raw[g1] * sd;

    float se2 = wredSum(errA * errA + errB * errB);
    float sn2 = wredSum(nsA * nsA + nsB * nsB);
    float rn = rsqrtf((se2 * (1.f / DD)) * (sn2 * (1.f / DD)) + 1e-6f);

    g_coef[g0]  = -errA * rn * plA * mkA;
    g_coef[g1]  = -errB * rn * plB * mkB;
    g_noisy[g0] = nsA;
    g_noisy[g1] = nsB;
}

// ---------------------------------------------------------------------------
// K5: fused grads + momentum + gaussian column mask + W update + row rms.
// 16 threads per row (float4 each), 16 rows per 256-thread block.
// Block order REVERSED so first-scheduled blocks touch the W region most
// recently streamed by k1 (LRU-friendly). M loads streaming (__ldcs),
// W-new stores streaming (__stcs); W loads default policy for L2 reuse.
// ---------------------------------------------------------------------------
__device__ __forceinline__ float newW(float w, float wlat, float m, float h, float g) {
    float grad = h + 0.01f * wlat - 0.01f * w;     // LAT_DECAY*W_lat - WD*W_self
    return w + 0.0033f * (m * 0.4f + 0.6f * grad * g);
}

__global__ void __launch_bounds__(256, 7) k5_update(
    const float* __restrict__ W1, const float* __restrict__ W2, const float* __restrict__ W3,
    const float* __restrict__ M1, const float* __restrict__ M2, const float* __restrict__ M3,
    float* __restrict__ out)
{
    int t   = threadIdx.x;
    int tx  = t & 15;
    int blk = (int)gridDim.x - 1 - (int)blockIdx.x;   // reversed walk
    int row = blk * 16 + (t >> 4);         // 0..BND-1  (b,n,i)
    int bn  = row >> 6;
    size_t b4 = (size_t)row * 16 + tx;     // float4 index into (BND x D) matrices

    float4 w1 = ((const float4*)W1)[b4];
    float4 w2 = ((const float4*)W2)[b4];
    float4 w3 = ((const float4*)W3)[b4];

    float  c  = g_coef[row];
    float4 ns = ((const float4*)g_noisy)[bn * 16 + tx];
    float4 gm = ((const float4*)g_gmask)[tx];
    float4 h  = { c * ns.x, c * ns.y, c * ns.z, c * ns.w };

    // --- W1 update ---
    {
        float4 m1 = __ldcs(((const float4*)M1) + b4);
        float4 t1;
        t1.x = newW(w1.x, w3.x, m1.x, h.x, gm.x);
        t1.y = newW(w1.y, w3.y, m1.y, h.y, gm.y);
        t1.z = newW(w1.z, w3.z, m1.z, h.z, gm.z);
        t1.w = newW(w1.w, w3.w, m1.w, h.w, gm.w);
        float s1 = t1.x*t1.x + t1.y*t1.y + t1.z*t1.z + t1.w*t1.w;
        #pragma unroll
        for (int o = 8; o; o >>= 1) s1 += __shfl_xor_sync(0xffffffffu, s1, o);
        float r1 = rsqrtf(s1 * (1.f / 64.f) + 1e-6f);
        float4 o1 = { t1.x*r1, t1.y*r1, t1.z*r1, t1.w*r1 };
        __stcs(((float4*)(out + OFF_W1)) + b4, o1);
    }
    // --- W2 update ---
    {
        float4 m2 = __ldcs(((const float4*)M2) + b4);
        float4 t2;
        t2.x = newW(w2.x, w1.x, m2.x, h.x, gm.x);
        t2.y = newW(w2.y, w1.y, m2.y, h.y, gm.y);
        t2.z = newW(w2.z, w1.z, m2.z, h.z, gm.z);
        t2.w = newW(w2.w, w1.w, m2.w, h.w, gm.w);
        float s2 = t2.x*t2.x + t2.y*t2.y + t2.z*t2.z + t2.w*t2.w;
        #pragma unroll
        for (int o = 8; o; o >>= 1) s2 += __shfl_xor_sync(0xffffffffu, s2, o);
        float r2 = rsqrtf(s2 * (1.f / 64.f) + 1e-6f);
        float4 o2 = { t2.x*r2, t2.y*r2, t2.z*r2, t2.w*r2 };
        __stcs(((float4*)(out + OFF_W2)) + b4, o2);
    }
    // --- W3 update ---
    {
        float4 m3 = __ldcs(((const float4*)M3) + b4);
        float4 t3;
        t3.x = newW(w3.x, w2.x, m3.x, h.x, gm.x);
        t3.y = newW(w3.y, w2.y, m3.y, h.y, gm.y);
        t3.z = newW(w3.z, w2.z, m3.z, h.z, gm.z);
        t3.w = newW(w3.w, w2.w, m3.w, h.w, gm.w);
        float s3 = t3.x*t3.x + t3.y*t3.y + t3.z*t3.z + t3.w*t3.w;
        #pragma unroll
        for (int o = 8; o; o >>= 1) s3 += __shfl_xor_sync(0xffffffffu, s3, o);
        float r3 = rsqrtf(s3 * (1.f / 64.f) + 1e-6f);
        float4 o3 = { t3.x*r3, t3.y*r3, t3.z*r3, t3.w*r3 };
        __stcs(((float4*)(out + OFF_W3)) + b4, o3);
    }
}

// ---------------------------------------------------------------------------
extern "C" void kernel_launch(void* const* d_in, const int* in_sizes, int n_in,
                              void* d_out, int out_size)
{
    const float* eye     = (const float*)d_in[0];
    const float* stomach = (const float*)d_in[1];
    const float* state   = (const float*)d_in[2];
    const float* outputv = (const float*)d_in[3];
    const float* W1      = (const float*)d_in[4];
    const float* W2      = (const float*)d_in[5];
    const float* W3      = (const float*)d_in[6];
    const float* M1      = (const float*)d_in[7];
    const float* M2      = (const float*)d_in[8];
    const float* M3      = (const float*)d_in[9];
    const float* Ebase   = (const float*)d_in[10];
    const float* A       = (const float*)d_in[11];
    const float* noiseA  = (const float*)d_in[12];
    const float* n1raw   = (const float*)d_in[13];
    const float* n2raw   = (const float*)d_in[14];
    const int*   stepc   = (const int*)d_in[15];
    float* out = (float*)d_out;

    k1_qkp<<<BN / 4, 192>>>(state, W1, W2, W3, out);
    k2_attn<<<BN, 128>>>(A, noiseA, outputv, eye, stomach, state, stepc, out);
    k4_coef<<<BN / 8, 256>>>(state, Ebase, n1raw, n2raw, out);
    k5_update<<<BND / 16, 256>>>(W1, W2, W3, M1, M2, M3, out);
}

// round 8
// speedup vs baseline: 1.2476x; 1.0078x over previous
#include <cuda_runtime.h>
#include <math.h>

#define BB 16
#define NN 128
#define DD 64
#define BN  2048        // BB*NN
#define BND 131072      // BN*DD
#define BNDD 8388608    // BND*DD

// out layout: prediction[BND], target[BND], A_new[BN*NN], W1n[BNDD], W2n[BNDD], W3n[BNDD]
#define OFF_T  (BND)
#define OFF_A  (2*BND)
#define OFF_W1 (4*BND)            // 2*BND + BN*NN = 4*BND
#define OFF_W2 (OFF_W1 + BNDD)
#define OFF_W3 (OFF_W2 + BNDD)

// scratch (static device globals; no allocation)
__device__ float g_q[BND];
__device__ float g_k[BND];
__device__ float g_coef[BND];
__device__ float g_noisy[BND];
__device__ float g_pbn_m[BN];
__device__ float g_pbn_e[BN];
__device__ float g_pbn_e2[BN];
__device__ float g_mag[BB];
__device__ float g_gmask[DD];
__device__ float g_std;
__device__ unsigned g_cnt = 0;

__device__ __forceinline__ float wredMax(float v) {
    #pragma unroll
    for (int o = 16; o; o >>= 1) v = fmaxf(v, __shfl_xor_sync(0xffffffffu, v, o));
    return v;
}
__device__ __forceinline__ float wredSum(float v) {
    #pragma unroll
    for (int o = 16; o; o >>= 1) v += __shfl_xor_sync(0xffffffffu, v, o);
    return v;
}

// ---------------------------------------------------------------------------
// K1: per (b,n) three matvecs: raw_pred = state@W1, k = state@W2, q = state@W3
// plus prediction elementwise. 16 threads x float4 per matvec output,
// 4 bn per 192-thread block -> 512 blocks, LDG.128 streaming.
// ---------------------------------------------------------------------------
__global__ void __launch_bounds__(192, 6) k1_qkp(
    const float* __restrict__ state,
    const float* __restrict__ W1, const float* __restrict__ W2, const float* __restrict__ W3,
    float* __restrict__ out)
{
    int t   = threadIdx.x;
    int sub = t / 48;         // 0..3 : bn within block
    int r   = t % 48;
    int x   = r >> 4;         // 0: W1(pred), 1: W2(k), 2: W3(q)
    int kk  = r & 15;         // float4 column group
    int bn  = blockIdx.x * 4 + sub;

    __shared__ float s[4][DD];
    for (int i = t; i < 4 * DD; i += 192)
        s[i >> 6][i & 63] = state[blockIdx.x * 4 * DD + i];
    __syncthreads();

    const float* Wp = (x == 0) ? W1 : ((x == 1) ? W2 : W3);
    const float4* Wb = (const float4*)(Wp + (size_t)bn * DD * DD) + kk;

    float4 acc = {0.f, 0.f, 0.f, 0.f};
    #pragma unroll 8
    for (int j = 0; j < DD; j++) {
        float  sv = s[sub][j];
        float4 w  = Wb[j * 16];
        acc.x += sv * w.x; acc.y += sv * w.y;
        acc.z += sv * w.z; acc.w += sv * w.w;
    }

    if (x == 0) {
        const float C = 1.8477590650225735f;  // sqrt(2+sqrt(2))
        float4 p;
        p.x = tanhf(acc.x - tanhf(acc.x) * 0.6f) * C;
        p.y = tanhf(acc.y - tanhf(acc.y) * 0.6f) * C;
        p.z = tanhf(acc.z - tanhf(acc.z) * 0.6f) * C;
        p.w = tanhf(acc.w - tanhf(acc.w) * 0.6f) * C;
        ((float4*)out)[bn * 16 + kk] = p;
    } else if (x == 1) {
        ((float4*)g_k)[bn * 16 + kk] = acc;
    } else {
        ((float4*)g_q)[bn * 16 + kk] = acc;
    }
}

// ---------------------------------------------------------------------------
// K2: attention row per block + fused global stats (state mag, err std,
// gaussian mask) via last-block-done. 2048 blocks x 128 threads.
// Target matvec vectorized: 16 float4 col-groups x 8 mm-partitions.
// ---------------------------------------------------------------------------
__global__ void __launch_bounds__(128) k2_attn(
    const float* __restrict__ A,
    const float* __restrict__ noiseA,
    const float* __restrict__ outputv,
    const float* __restrict__ eye,
    const float* __restrict__ stomach,
    const float* __restrict__ state,
    const int* __restrict__ stepc,
    float* __restrict__ out)
{
    int bn = blockIdx.x;
    int b  = bn >> 7;
    int n  = bn & 127;
    int m  = threadIdx.x;

    __shared__ float qs[DD];
    __shared__ float red[4];
    __shared__ float anew[NN];
    __shared__ float4 tp4[NN];
    __shared__ float ts[DD];

    float errv = 0.f, amv = 0.f;

    if (n < 2) {
        out[OFF_A + (size_t)bn * NN + m] = 0.f;
        if (m < DD) {
            float tv = (n == 0) ? eye[b * DD + m] : stomach[b * DD + m];
            out[OFF_T + bn * DD + m] = tv;
            errv = out[bn * DD + m] - tv;
            amv  = fabsf(state[bn * DD + m]);
        }
    } else {
        if (m < DD) qs[m] = g_q[bn * DD + m];
        __syncthreads();

        const float4* krow = (const float4*)(g_k + (size_t)(b * NN + m) * DD);
        float dot = 0.f;
        #pragma unroll
        for (int i = 0; i < DD / 4; i++) {
            float4 v = krow[i];
            dot += qs[4*i] * v.x + qs[4*i+1] * v.y + qs[4*i+2] * v.z + qs[4*i+3] * v.w;
        }
        float raw = dot * 0.125f + noiseA[(size_t)bn * NN + m] * 1e-5f;

        float v = wredMax(raw);
        if ((m & 31) == 0) red[m >> 5] = v;
        __syncthreads();
        float rowmax = fmaxf(fmaxf(red[0], red[1]), fmaxf(red[2], red[3]));
        __syncthreads();

        float e = expf(raw - rowmax);      // max element: e == 1.0f exactly
        v = wredSum(e);
        if ((m & 31) == 0) red[m >> 5] = v;
        __syncthreads();
        float sum = red[0] + red[1] + red[2] + red[3];
        __syncthreads();

        float pd    = e / sum;
        float maxpd = 1.0f / sum;          // == max(pd) bit-exactly

        bool keep = (pd > (1.0f / 129.0f)) || (pd == maxpd);
        float ek = keep ? e : 0.f;
        v = wredSum(ek);
        if ((m & 31) == 0) red[m >> 5] = v;
        __syncthreads();
        float sum2 = red[0] + red[1] + red[2] + red[3];
        __syncthreads();

        float P  = ek / sum2;
        float an = A[(size_t)bn * NN + m] * 0.99f + P * 0.01f;
        out[OFF_A + (size_t)bn * NN + m] = an;
        anew[m] = an;
        __syncthreads();

        // target matvec: thread = (cg = col float4 group 0..15, part = mm chunk 0..7)
        {
            int cg   = m & 15;
            int part = m >> 4;
            const float4* ov = (const float4*)outputv + ((size_t)(b * NN + part * 16) * 16 + cg);
            float4 acc = {0.f, 0.f, 0.f, 0.f};
            #pragma unroll
            for (int mm = 0; mm < 16; mm++) {
                float a  = anew[part * 16 + mm];
                float4 v = ov[mm * 16];
                acc.x += a * v.x; acc.y += a * v.y;
                acc.z += a * v.z; acc.w += a * v.w;
            }
            tp4[m] = acc;
        }
        __syncthreads();
        if (m < 16) {
            float4 s4 = tp4[m];
            #pragma unroll
            for (int p = 1; p < 8; p++) {
                float4 v = tp4[p * 16 + m];
                s4.x += v.x; s4.y += v.y; s4.z += v.z; s4.w += v.w;
            }
            ((float4*)ts)[m] = s4;
            ((float4*)(out + OFF_T + bn * DD))[m] = s4;
        }
        __syncthreads();
        if (m < DD) {
            float tv = ts[m];
            errv = out[bn * DD + m] - tv;
            amv  = fabsf(state[bn * DD + m]);
        }
    }

    // ---- per-bn stats partials (threads >= DD contribute zeros) ----
    {
        float ae  = wredSum(errv);
        float ae2 = wredSum(errv * errv);
        float am  = wredSum(amv);
        __shared__ float se[4], se2[4], sm[4];
        int w = m >> 5;
        if ((m & 31) == 0) { se[w] = ae; se2[w] = ae2; sm[w] = am; }
        __syncthreads();
        if (m == 0) {
            g_pbn_e[bn]  = se[0] + se[1] + se[2] + se[3];
            g_pbn_e2[bn] = se2[0] + se2[1] + se2[2] + se2[3];
            g_pbn_m[bn]  = sm[0] + sm[1] + sm[2] + sm[3];
        }
    }

    // ---- last-block final reduction ----
    __shared__ int isLast;
    __syncthreads();
    if (m == 0) {
        __threadfence();
        unsigned old = atomicAdd(&g_cnt, 1u);
        isLast = (old == (unsigned)(BN - 1)) ? 1 : 0;
    }
    __syncthreads();
    if (isLast) {
        // per-b mag: 8 lanes per b, each sums 16 entries, 8-lane shuffle combine
        {
            int bb = m >> 3, j = m & 7;
            float s = 0.f;
            int base = bb * NN + j * 16;
            #pragma unroll
            for (int i = 0; i < 16; i++) s += g_pbn_m[base + i];
            #pragma unroll
            for (int o = 4; o; o >>= 1) s += __shfl_xor_sync(0xffffffffu, s, o);
            if (j == 0) g_mag[bb] = s;
        }
        // global err sums: each thread sums 16, then block reduce
        {
            float e = 0.f, e2 = 0.f;
            int base = m * 16;
            #pragma unroll
            for (int i = 0; i < 16; i++) { e += g_pbn_e[base + i]; e2 += g_pbn_e2[base + i]; }
            e = wredSum(e); e2 = wredSum(e2);
            __shared__ float r0[4], r1[4];
            int w = m >> 5;
            if ((m & 31) == 0) { r0[w] = e; r1[w] = e2; }
            __syncthreads();
            if (m == 0) {
                float E  = r0[0] + r0[1] + r0[2] + r0[3];
                float E2 = r1[0] + r1[1] + r1[2] + r1[3];
                const float M = (float)BND;
                float var = (E2 - E * E / M) / (M - 1.0f);
                g_std = sqrtf(fmaxf(var, 0.f));
                g_cnt = 0u;   // reset for next graph replay
            }
        }
        // travelling gaussian column mask
        if (m < DD) {
            float scf    = (float)(*stepc) + 1.0f;
            float center = fmodf(scf * 0.5f, 64.0f);
            float d = fabsf((float)m - center);
            d = fminf(d, 64.f - d);
            g_gmask[m] = expf(-d * d / 0.020001f);
        }
    }
}

// ---------------------------------------------------------------------------
// K4: warp per (b,n): E_curr softmax over D, Eb EMA, plasticity/mask,
// noisy_state, outer-product rms factorization -> coef, noisy.
// 256 blocks x 256 threads (8 warps each); lane handles i and i+32.
// ---------------------------------------------------------------------------
__global__ void __launch_bounds__(256) k4_coef(
    const float* __restrict__ state,
    const float* __restrict__ Ebase,
    const float* __restrict__ n1raw,
    const float* __restrict__ n2raw,
    const float* __restrict__ out)
{
    int bn   = blockIdx.x * 8 + (threadIdx.x >> 5);
    int lane = threadIdx.x & 31;
    int b    = bn >> 7;
    int g0   = bn * DD + lane;
    int g1   = g0 + 32;

    float errA = out[g0] - out[OFF_T + g0];
    float errB = out[g1] - out[OFF_T + g1];

    float mx = wredMax(fmaxf(errA, errB));
    float exA = expf(errA - mx), exB = expf(errB - mx);
    float sm = wredSum(exA + exB);
    float EcA = exA / sm, EcB = exB / sm;

    float Eb0A = Ebase[g0], Eb0B = Ebase[g1];
    float EbA = (Eb0A == 0.f) ? EcA : Eb0A;
    float EbB = (Eb0B == 0.f) ? EcB : Eb0B;
    EbA = EbA * 0.95f + 0.05f * EcA;
    EbB = EbB * 0.95f + 0.05f * EcB;
    float advA = EcA - EbA, advB = EcB - EbB;
    float plA = 1.f + advA * rsqrtf(advA * advA + 1e-6f);
    float plB = 1.f + advB * rsqrtf(advB * advB + 1e-6f);
    float mkA = (EbA > 0.f) ? 1.f : 0.f;
    float mkB = (EbB > 0.f) ? 1.f : 0.f;

    float inv_mag = 1.f / (1.f + g_mag[b]);
    float sd = g_std * 0.8f;
    float nsA = state[g0] + n1raw[g0] * inv_mag + n2raw[g0] * sd;
    float nsB = state[g1] + n1raw[g1] * inv_mag + n2raw[g1] * sd;

    float se2 = wredSum(errA * errA + errB * errB);
    float sn2 = wredSum(nsA * nsA + nsB * nsB);
    float rn = rsqrtf((se2 * (1.f / DD)) * (sn2 * (1.f / DD)) + 1e-6f);

    g_coef[g0]  = -errA * rn * plA * mkA;
    g_coef[g1]  = -errB * rn * plB * mkB;
    g_noisy[g0] = nsA;
    g_noisy[g1] = nsB;
}

// ---------------------------------------------------------------------------
// K5: fused grads + momentum + gaussian column mask + W update + row rms.
// 16 threads per row (float4 each), 16 rows per 256-thread block.
// Reversed block walk for k1-L2 reuse; __ldcs on M, __stcs on stores.
// ---------------------------------------------------------------------------
__device__ __forceinline__ float newW(float w, float wlat, float m, float h, float g) {
    float grad = h + 0.01f * wlat - 0.01f * w;     // LAT_DECAY*W_lat - WD*W_self
    return w + 0.0033f * (m * 0.4f + 0.6f * grad * g);
}

__global__ void __launch_bounds__(256, 7) k5_update(
    const float* __restrict__ W1, const float* __restrict__ W2, const float* __restrict__ W3,
    const float* __restrict__ M1, const float* __restrict__ M2, const float* __restrict__ M3,
    float* __restrict__ out)
{
    int t   = threadIdx.x;
    int tx  = t & 15;
    int blk = (int)gridDim.x - 1 - (int)blockIdx.x;   // reversed walk
    int row = blk * 16 + (t >> 4);         // 0..BND-1  (b,n,i)
    int bn  = row >> 6;
    size_t b4 = (size_t)row * 16 + tx;     // float4 index into (BND x D) matrices

    float4 w1 = ((const float4*)W1)[b4];
    float4 w2 = ((const float4*)W2)[b4];
    float4 w3 = ((const float4*)W3)[b4];

    float  c  = g_coef[row];
    float4 ns = ((const float4*)g_noisy)[bn * 16 + tx];
    float4 gm = ((const float4*)g_gmask)[tx];
    float4 h  = { c * ns.x, c * ns.y, c * ns.z, c * ns.w };

    // --- W1 update ---
    {
        float4 m1 = __ldcs(((const float4*)M1) + b4);
        float4 t1;
        t1.x = newW(w1.x, w3.x, m1.x, h.x, gm.x);
        t1.y = newW(w1.y, w3.y, m1.y, h.y, gm.y);
        t1.z = newW(w1.z, w3.z, m1.z, h.z, gm.z);
        t1.w = newW(w1.w, w3.w, m1.w, h.w, gm.w);
        float s1 = t1.x*t1.x + t1.y*t1.y + t1.z*t1.z + t1.w*t1.w;
        #pragma unroll
        for (int o = 8; o; o >>= 1) s1 += __shfl_xor_sync(0xffffffffu, s1, o);
        float r1 = rsqrtf(s1 * (1.f / 64.f) + 1e-6f);
        float4 o1 = { t1.x*r1, t1.y*r1, t1.z*r1, t1.w*r1 };
        __stcs(((float4*)(out + OFF_W1)) + b4, o1);
    }
    // --- W2 update ---
    {
        float4 m2 = __ldcs(((const float4*)M2) + b4);
        float4 t2;
        t2.x = newW(w2.x, w1.x, m2.x, h.x, gm.x);
        t2.y = newW(w2.y, w1.y, m2.y, h.y, gm.y);
        t2.z = newW(w2.z, w1.z, m2.z, h.z, gm.z);
        t2.w = newW(w2.w, w1.w, m2.w, h.w, gm.w);
        float s2 = t2.x*t2.x + t2.y*t2.y + t2.z*t2.z + t2.w*t2.w;
        #pragma unroll
        for (int o = 8; o; o >>= 1) s2 += __shfl_xor_sync(0xffffffffu, s2, o);
        float r2 = rsqrtf(s2 * (1.f / 64.f) + 1e-6f);
        float4 o2 = { t2.x*r2, t2.y*r2, t2.z*r2, t2.w*r2 };
        __stcs(((float4*)(out + OFF_W2)) + b4, o2);
    }
    // --- W3 update ---
    {
        float4 m3 = __ldcs(((const float4*)M3) + b4);
        float4 t3;
        t3.x = newW(w3.x, w2.x, m3.x, h.x, gm.x);
        t3.y = newW(w3.y, w2.y, m3.y, h.y, gm.y);
        t3.z = newW(w3.z, w2.z, m3.z, h.z, gm.z);
        t3.w = newW(w3.w, w2.w, m3.w, h.w, gm.w);
        float s3 = t3.x*t3.x + t3.y*t3.y + t3.z*t3.z + t3.w*t3.w;
        #pragma unroll
        for (int o = 8; o; o >>= 1) s3 += __shfl_xor_sync(0xffffffffu, s3, o);
        float r3 = rsqrtf(s3 * (1.f / 64.f) + 1e-6f);
        float4 o3 = { t3.x*r3, t3.y*r3, t3.z*r3, t3.w*r3 };
        __stcs(((float4*)(out + OFF_W3)) + b4, o3);
    }
}

// ---------------------------------------------------------------------------
extern "C" void kernel_launch(void* const* d_in, const int* in_sizes, int n_in,
                              void* d_out, int out_size)
{
    const float* eye     = (const float*)d_in[0];
    const float* stomach = (const float*)d_in[1];
    const float* state   = (const float*)d_in[2];
    const float* outputv = (const float*)d_in[3];
    const float* W1      = (const float*)d_in[4];
    const float* W2      = (const float*)d_in[5];
    const float* W3      = (const float*)d_in[6];
    const float* M1      = (const float*)d_in[7];
    const float* M2      = (const float*)d_in[8];
    const float* M3      = (const float*)d_in[9];
    const float* Ebase   = (const float*)d_in[10];
    const float* A       = (const float*)d_in[11];
    const float* noiseA  = (const float*)d_in[12];
    const float* n1raw   = (const float*)d_in[13];
    const float* n2raw   = (const float*)d_in[14];
    const int*   stepc   = (const int*)d_in[15];
    float* out = (float*)d_out;

    k1_qkp<<<BN / 4, 192>>>(state, W1, W2, W3, out);
    k2_attn<<<BN, 128>>>(A, noiseA, outputv, eye, stomach, state, stepc, out);
    k4_coef<<<BN / 8, 256>>>(state, Ebase, n1raw, n2raw, out);
    k5_update<<<BND / 16, 256>>>(W1, W2, W3, M1, M2, M3, out);
}